// round 9
// baseline (speedup 1.0000x reference)
#include <cuda_runtime.h>

#define NGRAPH 1024
#define NPG    128
#define HID    64
#define EPG    2048            // edges per graph (NPG*16)
#define GT     512             // threads in GNN kernel
#define NW     (GT/32)         // 16 warps
#define KSPLIT 32              // head gemm k-splits

typedef unsigned long long ull;

// ---- f32x2 packed-FMA helpers ----
__device__ __forceinline__ ull pk1(float x) {
    ull r; asm("mov.b64 %0,{%1,%1};" : "=l"(r) : "f"(x)); return r;
}
__device__ __forceinline__ void fma2(ull& d, ull a, ull b) {
    asm("fma.rn.f32x2 %0,%1,%2,%0;" : "+l"(d) : "l"(a), "l"(b));
}
__device__ __forceinline__ float2 unpk(ull v) {
    float2 r; asm("mov.b64 {%0,%1},%2;" : "=f"(r.x), "=f"(r.y) : "l"(v)); return r;
}

// ---- global scratch ----
__device__ float g_h [(size_t)NGRAPH * NPG * HID];        // final node features [1024x8192]
__device__ float g_hp[KSPLIT][(size_t)NGRAPH * 128];      // head GEMM k-split partials

// ---- shared memory (~108.6KB -> 2 CTAs/SM) ----
struct SM {
    float  H[NPG * HID];       // 32KB node features (also xr in GATv2)
    float  A[NPG * HID];       // 32KB xl / xw
    float  W[HID * HID];       // 16KB weight tile
    float2 ae[EPG];            // 16KB CSR-ordered {exp(logit), src byte offset}
    float  xin[NPG * 4];       //  2KB
    float  vec0[HID], vec1[HID], vec2[HID], vec3[HID];
    float  lng[HID], lnb[HID];
    float  alS[NPG], alD[NPG], alE[NPG];
    int    off[NPG + 1];
    int    cnt[NPG];
    int    scanw[4];
    unsigned char csrc[EPG], cdst[EPG];
};

__device__ __forceinline__ float wsum(float v) {
#pragma unroll
    for (int o = 16; o; o >>= 1) v += __shfl_xor_sync(0xffffffffu, v, o);
    return v;
}

// CSR-run aggregate: acc += sum_j exp_j * A[src_j], ps += sum_j exp_j.
// ae.y holds src byte offset (s<<8); Ab = A base + lane*8. Paired LDS.128 ae loads.
__device__ __forceinline__ void seg_aggregate(const SM* sm, const char* Ab,
                                              int o0, int o1, ull& acc, float& ps)
{
    int j = o0;
    if (j < o1 && (j & 1)) {
        float2 t = sm->ae[j];
        fma2(acc, pk1(t.x), *(const ull*)(Ab + __float_as_int(t.y)));
        ps += t.x; j++;
    }
    for (; j + 1 < o1; j += 2) {
        float4 t2 = *(const float4*)&sm->ae[j];
        fma2(acc, pk1(t2.x), *(const ull*)(Ab + __float_as_int(t2.y)));
        fma2(acc, pk1(t2.z), *(const ull*)(Ab + __float_as_int(t2.w)));
        ps += t2.x + t2.z;
    }
    if (j < o1) {
        float2 t = sm->ae[j];
        fma2(acc, pk1(t.x), *(const ull*)(Ab + __float_as_int(t.y)));
        ps += t.x;
    }
}

// 64x64 GEMM (A = H @ W) with fused attention-scalar epilogue.
// Warp w owns rows 8w..8w+7; lane owns col pair (2l,2l+1).
__device__ __forceinline__ void gemm64_att(SM* sm, int wid, int lane)
{
    int r0 = wid * 8;
    ull acc[8];
#pragma unroll
    for (int r = 0; r < 8; r++) acc[r] = 0ull;
    const float* Wb = sm->W + lane * 2;
#pragma unroll 2
    for (int k = 0; k < HID; k += 4) {
        ull w0 = *(const ull*)&Wb[(k + 0) * HID];
        ull w1 = *(const ull*)&Wb[(k + 1) * HID];
        ull w2 = *(const ull*)&Wb[(k + 2) * HID];
        ull w3 = *(const ull*)&Wb[(k + 3) * HID];
#pragma unroll
        for (int r = 0; r < 8; r++) {
            float4 h = *(const float4*)&sm->H[(r0 + r) * HID + k];
            fma2(acc[r], pk1(h.x), w0);
            fma2(acc[r], pk1(h.y), w1);
            fma2(acc[r], pk1(h.z), w2);
            fma2(acc[r], pk1(h.w), w3);
        }
    }
    float2 s2 = *(const float2*)&sm->vec0[lane * 2];
    float2 d2 = *(const float2*)&sm->vec1[lane * 2];
    float ps[8], pd[8];
#pragma unroll
    for (int r = 0; r < 8; r++) {
        *(ull*)&sm->A[(r0 + r) * HID + lane * 2] = acc[r];
        float2 a = unpk(acc[r]);
        ps[r] = a.x * s2.x + a.y * s2.y;
        pd[r] = a.x * d2.x + a.y * d2.y;
    }
#pragma unroll
    for (int o = 16; o; o >>= 1) {
#pragma unroll
        for (int r = 0; r < 8; r++) {
            ps[r] += __shfl_xor_sync(0xffffffffu, ps[r], o);
            pd[r] += __shfl_xor_sync(0xffffffffu, pd[r], o);
        }
    }
    if (lane < 8) {
        int v = r0 + lane;
        float a = ps[lane], b = pd[lane];
        sm->alS[v] = a;
        sm->alD[v] = b;
        float t = a + b;
        sm->alE[v] = __expf(fmaf(0.4f, fabsf(t), 0.6f * t));   // exp(lrelu(t,0.2))
    }
}

// ---- one GATConv layer (with self-loops), fully in SMEM ----
__device__ void gat_layer(SM* sm, const float* __restrict__ Wg,
                          const float* __restrict__ as_, const float* __restrict__ ad_,
                          const float* __restrict__ bias,
                          int tid, int wid, int lane)
{
    for (int i = tid; i < HID * HID; i += GT) sm->W[i] = Wg[i];
    if (tid < HID) { sm->vec0[tid] = as_[tid]; sm->vec1[tid] = ad_[tid]; sm->vec2[tid] = bias[tid]; }
    __syncthreads();

    gemm64_att(sm, wid, lane);     // A = H @ W, plus alS/alD/alE
    __syncthreads();

    // fused logit+exp pass (edge-parallel)
#pragma unroll
    for (int i = tid; i < EPG; i += GT) {
        int s = sm->csrc[i], d = sm->cdst[i];
        float t = sm->alS[s] + sm->alD[d];
        float2 w;
        w.x = __expf(fmaf(0.4f, fabsf(t), 0.6f * t));
        w.y = __int_as_float(s << 8);
        sm->ae[i] = w;
    }
    __syncthreads();

    // single-pass aggregate + normalize (warp per destination)
    const char* Ab = (const char*)sm->A + lane * 8;
    for (int v = wid; v < NPG; v += NW) {
        ull acc = 0ull; float ps = 0.f;
        seg_aggregate(sm, Ab, sm->off[v], sm->off[v + 1], acc, ps);
        float el = sm->alE[v];
        fma2(acc, pk1(el), *(const ull*)(Ab + (v << 8)));
        float inv = __fdividef(1.f, ps + el + 1e-16f);
        float2 r  = unpk(acc);
        float2 b2 = *(const float2*)&sm->vec2[lane * 2];
        float2 o;
        o.x = fmaxf(fmaf(r.x, inv, b2.x), 0.f);
        o.y = fmaxf(fmaf(r.y, inv, b2.y), 0.f);
        *(float2*)&sm->H[v * HID + lane * 2] = o;
    }
    __syncthreads();
}

// ---- kernel 1: full 3-layer GNN, one CTA per graph, 2 CTAs/SM ----
__global__ void __launch_bounds__(GT, 2) gnn_kernel(
    const float* __restrict__ x, const int* __restrict__ ei,
    const float* __restrict__ Wl, const float* __restrict__ bl,
    const float* __restrict__ Wr, const float* __restrict__ br,
    const float* __restrict__ attv, const float* __restrict__ bv2,
    const float* __restrict__ Wg1, const float* __restrict__ as1,
    const float* __restrict__ ad1, const float* __restrict__ bg1,
    const float* __restrict__ Wg2, const float* __restrict__ as2,
    const float* __restrict__ ad2, const float* __restrict__ bg2,
    const float* __restrict__ lngp, const float* __restrict__ lnbp)
{
    extern __shared__ char smraw[];
    SM* sm = (SM*)smraw;
    int tid = threadIdx.x, lane = tid & 31, wid = tid >> 5;
    int g = blockIdx.x, base = g * NPG;
    const int* srcp = ei + (size_t)g * EPG;
    const int* dstp = ei + (size_t)NGRAPH * EPG + (size_t)g * EPG;

    // ---- load inputs, count in-degrees ----
    for (int i = tid; i < NPG * 4; i += GT) sm->xin[i] = x[(size_t)base * 4 + i];
    if (tid < HID) { sm->lng[tid] = lngp[tid]; sm->lnb[tid] = lnbp[tid]; }
    for (int i = tid; i < NPG; i += GT) sm->cnt[i] = 0;
    __syncthreads();
    for (int i = tid; i < EPG; i += GT) atomicAdd(&sm->cnt[dstp[i] - base], 1);
    __syncthreads();

    // exclusive scan of counts -> off
    int myv = 0, sc = 0;
    if (tid < NPG) {
        myv = sm->cnt[tid]; sc = myv;
#pragma unroll
        for (int o = 1; o < 32; o <<= 1) {
            int n = __shfl_up_sync(0xffffffffu, sc, o);
            if (lane >= o) sc += n;
        }
        if (lane == 31) sm->scanw[wid] = sc;
    }
    __syncthreads();
    if (tid < NPG) {
        int add = 0;
        for (int i = 0; i < wid; i++) add += sm->scanw[i];
        sm->off[tid] = add + sc - myv;
    }
    if (tid == 0) sm->off[NPG] = EPG;
    __syncthreads();
    if (tid < NPG) sm->cnt[tid] = sm->off[tid];
    __syncthreads();
    // scatter into materialized CSR
    for (int i = tid; i < EPG; i += GT) {
        int s = srcp[i] - base, d = dstp[i] - base;
        int pos = atomicAdd(&sm->cnt[d], 1);
        sm->csrc[pos] = (unsigned char)s;
        sm->cdst[pos] = (unsigned char)d;
    }

    // ---- GATv2 layer ----
    for (int i = tid; i < 4 * HID; i += GT) { sm->W[i] = Wl[i]; sm->W[4 * HID + i] = Wr[i]; }
    if (tid < HID) { sm->vec0[tid] = bl[tid]; sm->vec1[tid] = br[tid];
                     sm->vec2[tid] = attv[tid]; sm->vec3[tid] = bv2[tid]; }
    __syncthreads();
    {   // xl -> A, xr -> H  (IN = 4, tiny)
        int k = tid & (HID - 1), vg = tid >> 6;
#pragma unroll 4
        for (int r = 0; r < 16; r++) {
            int v = vg * 16 + r;
            float a = sm->vec0[k], b = sm->vec1[k];
#pragma unroll
            for (int i = 0; i < 4; i++) {
                float xv = sm->xin[v * 4 + i];
                a = fmaf(xv, sm->W[i * HID + k], a);
                b = fmaf(xv, sm->W[4 * HID + i * HID + k], b);
            }
            sm->A[v * HID + k] = a;
            sm->H[v * HID + k] = b;
        }
    }
    __syncthreads();
    // v2 logits+exp: warp per dst, xr cached in regs, half-warp per edge.
    // lrelu(s)*a = 0.6*s*a + 0.4*|s|*a
    {
        int hl = lane & 15, half = lane >> 4;
        float4 at = *(const float4*)&sm->vec2[hl * 4];
        for (int v = wid; v < NPG; v += NW) {
            int o0 = sm->off[v], o1 = sm->off[v + 1];
            float4 xr = *(const float4*)&sm->H[v * HID + hl * 4];
            for (int jj = o0; jj < o1; jj += 2) {
                int j = jj + half;
                bool valid = (j < o1);
                int s = sm->csrc[valid ? j : jj];
                float4 xl = *(const float4*)&sm->A[s * HID + hl * 4];
                float s0 = xl.x + xr.x, s1 = xl.y + xr.y;
                float s2 = xl.z + xr.z, s3 = xl.w + xr.w;
                float p = fmaf(s0, at.x, fmaf(s1, at.y, fmaf(s2, at.z, s3 * at.w)));
                float q = fmaf(fabsf(s0), at.x, fmaf(fabsf(s1), at.y,
                          fmaf(fabsf(s2), at.z, fabsf(s3) * at.w)));
                float t = fmaf(0.4f, q, 0.6f * p);
#pragma unroll
                for (int o = 8; o; o >>= 1) t += __shfl_xor_sync(0xffffffffu, t, o);
                if (hl == 0 && valid)
                    sm->ae[j] = make_float2(__expf(t), __int_as_float(s << 8));
            }
        }
    }
    __syncthreads();
    // aggregate + bias + lrelu(0.01) + layernorm -> H   (no self-loop in GATv2)
    {
        const char* Ab = (const char*)sm->A + lane * 8;
        for (int v = wid; v < NPG; v += NW) {
            ull acc = 0ull; float ps = 0.f;
            seg_aggregate(sm, Ab, sm->off[v], sm->off[v + 1], acc, ps);
            float inv = __fdividef(1.f, ps + 1e-16f);
            float2 r  = unpk(acc);
            float2 b2 = *(const float2*)&sm->vec3[lane * 2];
            float u0 = fmaf(r.x, inv, b2.x);
            float u1 = fmaf(r.y, inv, b2.y);
            float t0 = fmaf(0.495f, fabsf(u0), 0.505f * u0);   // lrelu 0.01
            float t1 = fmaf(0.495f, fabsf(u1), 0.505f * u1);
            float mean = wsum(t0 + t1) * (1.f / 64.f);
            float d0 = t0 - mean, d1 = t1 - mean;
            float var = wsum(d0 * d0 + d1 * d1) * (1.f / 64.f);
            float rstd = rsqrtf(var + 1e-5f);
            float2 gg = *(const float2*)&sm->lng[lane * 2];
            float2 bb = *(const float2*)&sm->lnb[lane * 2];
            float2 o;
            o.x = fmaf(d0 * rstd, gg.x, bb.x);
            o.y = fmaf(d1 * rstd, gg.y, bb.y);
            *(float2*)&sm->H[v * HID + lane * 2] = o;
        }
    }
    __syncthreads();

    // ---- GAT layers 1 & 2 ----
    gat_layer(sm, Wg1, as1, ad1, bg1, tid, wid, lane);
    gat_layer(sm, Wg2, as2, ad2, bg2, tid, wid, lane);

    // ---- write final features ----
    const float4* Hv = (const float4*)sm->H;
    float4* outp = (float4*)(g_h + (size_t)g * NPG * HID);
    for (int i = tid; i < NPG * HID / 4; i += GT) outp[i] = Hv[i];
}

// ---- kernel 2: split-K GEMM  partials[ky] = h[1024,8192(slice)] @ W1, FFMA2 inner ----
__global__ void __launch_bounds__(256) head_gemm(const float* __restrict__ W1)
{
    __shared__ float As[64][16];
    __shared__ float Bs[16][128];
    int m0 = blockIdx.x * 64;
    int ky = blockIdx.y;
    int kbase = ky * (8192 / KSPLIT);
    int tid = threadIdx.x;
    int tx = tid & 15, ty = tid >> 4;
    int r0 = ty * 4, c0 = tx * 8;
    ull acc[4][4];
#pragma unroll
    for (int r = 0; r < 4; r++)
#pragma unroll
        for (int c = 0; c < 4; c++) acc[r][c] = 0ull;

    int ar = tid >> 2, aq = (tid & 3) * 4;
    int brr = tid >> 4, bc = (tid & 15) * 8;
    for (int kk = kbase; kk < kbase + 8192 / KSPLIT; kk += 16) {
        *(float4*)&As[ar][aq]      = *(const float4*)&g_h[(size_t)(m0 + ar) * 8192 + kk + aq];
        *(float4*)&Bs[brr][bc]     = *(const float4*)&W1[(size_t)(kk + brr) * 128 + bc];
        *(float4*)&Bs[brr][bc + 4] = *(const float4*)&W1[(size_t)(kk + brr) * 128 + bc + 4];
        __syncthreads();
#pragma unroll
        for (int k = 0; k < 16; k++) {
            ull a0 = pk1(As[r0][k]),     a1 = pk1(As[r0 + 1][k]);
            ull a2 = pk1(As[r0 + 2][k]), a3 = pk1(As[r0 + 3][k]);
            ull b0 = *(const ull*)&Bs[k][c0];
            ull b1 = *(const ull*)&Bs[k][c0 + 2];
            ull b2 = *(const ull*)&Bs[k][c0 + 4];
            ull b3 = *(const ull*)&Bs[k][c0 + 6];
            fma2(acc[0][0], a0, b0); fma2(acc[0][1], a0, b1); fma2(acc[0][2], a0, b2); fma2(acc[0][3], a0, b3);
            fma2(acc[1][0], a1, b0); fma2(acc[1][1], a1, b1); fma2(acc[1][2], a1, b2); fma2(acc[1][3], a1, b3);
            fma2(acc[2][0], a2, b0); fma2(acc[2][1], a2, b1); fma2(acc[2][2], a2, b2); fma2(acc[2][3], a2, b3);
            fma2(acc[3][0], a3, b0); fma2(acc[3][1], a3, b1); fma2(acc[3][2], a3, b2); fma2(acc[3][3], a3, b3);
        }
        __syncthreads();
    }
    float* outp = g_hp[ky];
#pragma unroll
    for (int r = 0; r < 4; r++)
#pragma unroll
        for (int c = 0; c < 4; c++)
            *(ull*)&outp[(m0 + r0 + r) * 128 + c0 + 2 * c] = acc[r][c];
}

// ---- kernel 3: reduce partials + bias, lrelu, @W2, sigmoid; one warp per graph ----
__global__ void head_final(const float* __restrict__ W2, const float* __restrict__ b2,
                           const float* __restrict__ b1, float* __restrict__ outp)
{
    int g = blockIdx.x * 8 + (threadIdx.x >> 5);
    int lane = threadIdx.x & 31;
    float4 s = make_float4(0.f, 0.f, 0.f, 0.f);
#pragma unroll
    for (int ky = 0; ky < KSPLIT; ky++) {
        float4 p = *(const float4*)&g_hp[ky][(size_t)g * 128 + lane * 4];
        s.x += p.x; s.y += p.y; s.z += p.z; s.w += p.w;
    }
    float4 bb = *(const float4*)&b1[lane * 4];
    s.x += bb.x; s.y += bb.y; s.z += bb.z; s.w += bb.w;
    s.x = fmaf(0.495f, fabsf(s.x), 0.505f * s.x);
    s.y = fmaf(0.495f, fabsf(s.y), 0.505f * s.y);
    s.z = fmaf(0.495f, fabsf(s.z), 0.505f * s.z);
    s.w = fmaf(0.495f, fabsf(s.w), 0.505f * s.w);
    float4 w = *(const float4*)&W2[lane * 4];
    float p = s.x * w.x + s.y * w.y + s.z * w.z + s.w * w.w;
    p = wsum(p);
    if (lane == 0) outp[g] = 1.f / (1.f + expf(-(p + b2[0])));
}

extern "C" void kernel_launch(void* const* d_in, const int* in_sizes, int n_in,
                              void* d_out, int out_size)
{
    const float* x    = (const float*)d_in[0];
    const int*   ei   = (const int*)  d_in[1];
    const float* Wl   = (const float*)d_in[2];
    const float* bl   = (const float*)d_in[3];
    const float* Wr   = (const float*)d_in[4];
    const float* br   = (const float*)d_in[5];
    const float* attv = (const float*)d_in[6];
    const float* bv2  = (const float*)d_in[7];
    const float* Wg1  = (const float*)d_in[8];
    const float* as1  = (const float*)d_in[9];
    const float* ad1  = (const float*)d_in[10];
    const float* bg1  = (const float*)d_in[11];
    const float* Wg2  = (const float*)d_in[12];
    const float* as2  = (const float*)d_in[13];
    const float* ad2  = (const float*)d_in[14];
    const float* bg2  = (const float*)d_in[15];
    const float* lng  = (const float*)d_in[16];
    const float* lnb  = (const float*)d_in[17];
    const float* W1   = (const float*)d_in[18];
    const float* b1   = (const float*)d_in[19];
    const float* W2   = (const float*)d_in[20];
    const float* b2   = (const float*)d_in[21];
    float* outp = (float*)d_out;

    int smem = (int)sizeof(SM);
    cudaFuncSetAttribute(gnn_kernel, cudaFuncAttributeMaxDynamicSharedMemorySize, smem);

    gnn_kernel<<<NGRAPH, GT, smem>>>(x, ei, Wl, bl, Wr, br, attv, bv2,
                                     Wg1, as1, ad1, bg1, Wg2, as2, ad2, bg2, lng, lnb);
    head_gemm<<<dim3(16, KSPLIT), 256>>>(W1);
    head_final<<<NGRAPH / 8, 256>>>(W2, b2, b1, outp);
}

// round 10
// speedup vs baseline: 1.0407x; 1.0407x over previous
#include <cuda_runtime.h>

#define NGRAPH 1024
#define NPG    128
#define HID    64
#define EPG    2048            // edges per graph (NPG*16)
#define GT     512             // threads in GNN kernel
#define NW     (GT/32)         // 16 warps
#define KSPLIT 32              // head gemm k-splits

typedef unsigned long long ull;

// ---- f32x2 packed-FMA helpers ----
__device__ __forceinline__ ull pk1(float x) {
    ull r; asm("mov.b64 %0,{%1,%1};" : "=l"(r) : "f"(x)); return r;
}
__device__ __forceinline__ void fma2(ull& d, ull a, ull b) {
    asm("fma.rn.f32x2 %0,%1,%2,%0;" : "+l"(d) : "l"(a), "l"(b));
}
__device__ __forceinline__ float2 unpk(ull v) {
    float2 r; asm("mov.b64 {%0,%1},%2;" : "=f"(r.x), "=f"(r.y) : "l"(v)); return r;
}

// ---- global scratch ----
__device__ float g_h [(size_t)NGRAPH * NPG * HID];        // final node features [1024x8192]
__device__ float g_hp[KSPLIT][(size_t)NGRAPH * 128];      // head GEMM k-split partials

// ---- shared memory (~108.6KB -> 2 CTAs/SM) ----
struct SM {
    float  H[NPG * HID];       // 32KB node features (also xr in GATv2)
    float  A[NPG * HID];       // 32KB xl / xw
    float  W[HID * HID];       // 16KB weight tile
    float2 ae[EPG];            // 16KB CSR-ordered {exp(logit), src byte offset}
    float  xin[NPG * 4];       //  2KB
    float  vec0[HID], vec1[HID], vec2[HID], vec3[HID];
    float  lng[HID], lnb[HID];
    float  alS[NPG], alD[NPG], alE[NPG];
    int    off[NPG + 1];
    int    cnt[NPG];
    int    scanw[4];
    unsigned short csd[EPG];   // 4KB CSR-ordered packed (s | d<<8)
};

__device__ __forceinline__ float wsum(float v) {
#pragma unroll
    for (int o = 16; o; o >>= 1) v += __shfl_xor_sync(0xffffffffu, v, o);
    return v;
}

// CSR-run aggregate: acc += sum_j exp_j * A[src_j], ps += sum_j exp_j.
// ae.y holds src byte offset (s<<8); Ab = A base + lane*8. Paired LDS.128 ae loads.
__device__ __forceinline__ void seg_aggregate(const SM* sm, const char* Ab,
                                              int o0, int o1, ull& acc, float& ps)
{
    int j = o0;
    if (j < o1 && (j & 1)) {
        float2 t = sm->ae[j];
        fma2(acc, pk1(t.x), *(const ull*)(Ab + __float_as_int(t.y)));
        ps += t.x; j++;
    }
    for (; j + 1 < o1; j += 2) {
        float4 t2 = *(const float4*)&sm->ae[j];
        fma2(acc, pk1(t2.x), *(const ull*)(Ab + __float_as_int(t2.y)));
        fma2(acc, pk1(t2.z), *(const ull*)(Ab + __float_as_int(t2.w)));
        ps += t2.x + t2.z;
    }
    if (j < o1) {
        float2 t = sm->ae[j];
        fma2(acc, pk1(t.x), *(const ull*)(Ab + __float_as_int(t.y)));
        ps += t.x;
    }
}

// 64x64 GEMM (A = H @ W) with fused attention-scalar epilogue.
// Warp w owns rows 8w..8w+7; lane owns col pair (2l,2l+1).
__device__ __forceinline__ void gemm64_att(SM* sm, int wid, int lane)
{
    int r0 = wid * 8;
    ull acc[8];
#pragma unroll
    for (int r = 0; r < 8; r++) acc[r] = 0ull;
    const float* Wb = sm->W + lane * 2;
#pragma unroll 2
    for (int k = 0; k < HID; k += 4) {
        ull w0 = *(const ull*)&Wb[(k + 0) * HID];
        ull w1 = *(const ull*)&Wb[(k + 1) * HID];
        ull w2 = *(const ull*)&Wb[(k + 2) * HID];
        ull w3 = *(const ull*)&Wb[(k + 3) * HID];
#pragma unroll
        for (int r = 0; r < 8; r++) {
            float4 h = *(const float4*)&sm->H[(r0 + r) * HID + k];
            fma2(acc[r], pk1(h.x), w0);
            fma2(acc[r], pk1(h.y), w1);
            fma2(acc[r], pk1(h.z), w2);
            fma2(acc[r], pk1(h.w), w3);
        }
    }
    float2 s2 = *(const float2*)&sm->vec0[lane * 2];
    float2 d2 = *(const float2*)&sm->vec1[lane * 2];
    float ps[8], pd[8];
#pragma unroll
    for (int r = 0; r < 8; r++) {
        *(ull*)&sm->A[(r0 + r) * HID + lane * 2] = acc[r];
        float2 a = unpk(acc[r]);
        ps[r] = a.x * s2.x + a.y * s2.y;
        pd[r] = a.x * d2.x + a.y * d2.y;
    }
#pragma unroll
    for (int o = 16; o; o >>= 1) {
#pragma unroll
        for (int r = 0; r < 8; r++) {
            ps[r] += __shfl_xor_sync(0xffffffffu, ps[r], o);
            pd[r] += __shfl_xor_sync(0xffffffffu, pd[r], o);
        }
    }
    if (lane < 8) {
        int v = r0 + lane;
        float a = ps[lane], b = pd[lane];
        sm->alS[v] = a;
        sm->alD[v] = b;
        float t = a + b;
        sm->alE[v] = __expf(fmaf(0.4f, fabsf(t), 0.6f * t));   // exp(lrelu(t,0.2))
    }
}

// ---- one GATConv layer (with self-loops), fully in SMEM ----
__device__ void gat_layer(SM* sm, const float* __restrict__ Wg,
                          const float* __restrict__ as_, const float* __restrict__ ad_,
                          const float* __restrict__ bias,
                          int tid, int wid, int lane)
{
    for (int i = tid; i < HID * HID; i += GT) sm->W[i] = Wg[i];
    if (tid < HID) { sm->vec0[tid] = as_[tid]; sm->vec1[tid] = ad_[tid]; sm->vec2[tid] = bias[tid]; }
    __syncthreads();

    gemm64_att(sm, wid, lane);     // A = H @ W, plus alS/alD/alE
    __syncthreads();

    // fused logit+exp pass (edge-parallel); one LDS.16 gives both s and d
#pragma unroll
    for (int i = tid; i < EPG; i += GT) {
        int sd = sm->csd[i];
        int s = sd & 255, d = sd >> 8;
        float t = sm->alS[s] + sm->alD[d];
        float2 w;
        w.x = __expf(fmaf(0.4f, fabsf(t), 0.6f * t));
        w.y = __int_as_float(s << 8);
        sm->ae[i] = w;
    }
    __syncthreads();

    // single-pass aggregate + normalize (warp per destination)
    const char* Ab = (const char*)sm->A + lane * 8;
    for (int v = wid; v < NPG; v += NW) {
        ull acc = 0ull; float ps = 0.f;
        seg_aggregate(sm, Ab, sm->off[v], sm->off[v + 1], acc, ps);
        float el = sm->alE[v];
        fma2(acc, pk1(el), *(const ull*)(Ab + (v << 8)));
        float inv = __fdividef(1.f, ps + el + 1e-16f);
        float2 r  = unpk(acc);
        float2 b2 = *(const float2*)&sm->vec2[lane * 2];
        float2 o;
        o.x = fmaxf(fmaf(r.x, inv, b2.x), 0.f);
        o.y = fmaxf(fmaf(r.y, inv, b2.y), 0.f);
        *(float2*)&sm->H[v * HID + lane * 2] = o;
    }
    __syncthreads();
}

// ---- kernel 1: full 3-layer GNN, one CTA per graph, 2 CTAs/SM ----
__global__ void __launch_bounds__(GT, 2) gnn_kernel(
    const float* __restrict__ x, const int* __restrict__ ei,
    const float* __restrict__ Wl, const float* __restrict__ bl,
    const float* __restrict__ Wr, const float* __restrict__ br,
    const float* __restrict__ attv, const float* __restrict__ bv2,
    const float* __restrict__ Wg1, const float* __restrict__ as1,
    const float* __restrict__ ad1, const float* __restrict__ bg1,
    const float* __restrict__ Wg2, const float* __restrict__ as2,
    const float* __restrict__ ad2, const float* __restrict__ bg2,
    const float* __restrict__ lngp, const float* __restrict__ lnbp)
{
    extern __shared__ char smraw[];
    SM* sm = (SM*)smraw;
    int tid = threadIdx.x, lane = tid & 31, wid = tid >> 5;
    int g = blockIdx.x, base = g * NPG;
    const int* srcp = ei + (size_t)g * EPG;
    const int* dstp = ei + (size_t)NGRAPH * EPG + (size_t)g * EPG;

    // ---- load inputs, count in-degrees ----
    for (int i = tid; i < NPG * 4; i += GT) sm->xin[i] = x[(size_t)base * 4 + i];
    if (tid < HID) { sm->lng[tid] = lngp[tid]; sm->lnb[tid] = lnbp[tid]; }
    for (int i = tid; i < NPG; i += GT) sm->cnt[i] = 0;
    __syncthreads();
    for (int i = tid; i < EPG; i += GT) atomicAdd(&sm->cnt[dstp[i] - base], 1);
    __syncthreads();

    // exclusive scan of counts -> off
    int myv = 0, sc = 0;
    if (tid < NPG) {
        myv = sm->cnt[tid]; sc = myv;
#pragma unroll
        for (int o = 1; o < 32; o <<= 1) {
            int n = __shfl_up_sync(0xffffffffu, sc, o);
            if (lane >= o) sc += n;
        }
        if (lane == 31) sm->scanw[wid] = sc;
    }
    __syncthreads();
    if (tid < NPG) {
        int add = 0;
        for (int i = 0; i < wid; i++) add += sm->scanw[i];
        sm->off[tid] = add + sc - myv;
    }
    if (tid == 0) sm->off[NPG] = EPG;
    __syncthreads();
    if (tid < NPG) sm->cnt[tid] = sm->off[tid];
    __syncthreads();
    // scatter into materialized CSR: single u16 store per edge
    for (int i = tid; i < EPG; i += GT) {
        int s = srcp[i] - base, d = dstp[i] - base;
        int pos = atomicAdd(&sm->cnt[d], 1);
        sm->csd[pos] = (unsigned short)(s | (d << 8));
    }

    // ---- GATv2 layer ----
    for (int i = tid; i < 4 * HID; i += GT) { sm->W[i] = Wl[i]; sm->W[4 * HID + i] = Wr[i]; }
    if (tid < HID) { sm->vec0[tid] = bl[tid]; sm->vec1[tid] = br[tid];
                     sm->vec2[tid] = attv[tid]; sm->vec3[tid] = bv2[tid]; }
    __syncthreads();
    {   // xl -> A, xr -> H  (IN = 4, tiny)
        int k = tid & (HID - 1), vg = tid >> 6;
#pragma unroll 4
        for (int r = 0; r < 16; r++) {
            int v = vg * 16 + r;
            float a = sm->vec0[k], b = sm->vec1[k];
#pragma unroll
            for (int i = 0; i < 4; i++) {
                float xv = sm->xin[v * 4 + i];
                a = fmaf(xv, sm->W[i * HID + k], a);
                b = fmaf(xv, sm->W[4 * HID + i * HID + k], b);
            }
            sm->A[v * HID + k] = a;
            sm->H[v * HID + k] = b;
        }
    }
    __syncthreads();
    // v2 logits fused with exp: half-warp per edge (edge-parallel, R7-best form).
    // lrelu(s)*a = 0.6*s*a + 0.4*|s|*a
    {
        int hl = lane & 15;
        float4 at = *(const float4*)&sm->vec2[hl * 4];
#pragma unroll 2
        for (int j = wid * 2 + (lane >> 4); j < EPG; j += NW * 2) {
            int sd = sm->csd[j];
            int s = sd & 255, d = sd >> 8;
            float4 xl = *(const float4*)&sm->A[s * HID + hl * 4];
            float4 xr = *(const float4*)&sm->H[d * HID + hl * 4];
            float s0 = xl.x + xr.x, s1 = xl.y + xr.y;
            float s2 = xl.z + xr.z, s3 = xl.w + xr.w;
            float p = fmaf(s0, at.x, fmaf(s1, at.y, fmaf(s2, at.z, s3 * at.w)));
            float q = fmaf(fabsf(s0), at.x, fmaf(fabsf(s1), at.y,
                      fmaf(fabsf(s2), at.z, fabsf(s3) * at.w)));
            float t = fmaf(0.4f, q, 0.6f * p);
#pragma unroll
            for (int o = 8; o; o >>= 1) t += __shfl_xor_sync(0xffffffffu, t, o);
            if (hl == 0)
                sm->ae[j] = make_float2(__expf(t), __int_as_float(s << 8));
        }
    }
    __syncthreads();
    // aggregate + bias + lrelu(0.01) + layernorm -> H   (no self-loop in GATv2)
    {
        const char* Ab = (const char*)sm->A + lane * 8;
        for (int v = wid; v < NPG; v += NW) {
            ull acc = 0ull; float ps = 0.f;
            seg_aggregate(sm, Ab, sm->off[v], sm->off[v + 1], acc, ps);
            float inv = __fdividef(1.f, ps + 1e-16f);
            float2 r  = unpk(acc);
            float2 b2 = *(const float2*)&sm->vec3[lane * 2];
            float u0 = fmaf(r.x, inv, b2.x);
            float u1 = fmaf(r.y, inv, b2.y);
            float t0 = fmaf(0.495f, fabsf(u0), 0.505f * u0);   // lrelu 0.01
            float t1 = fmaf(0.495f, fabsf(u1), 0.505f * u1);
            float mean = wsum(t0 + t1) * (1.f / 64.f);
            float d0 = t0 - mean, d1 = t1 - mean;
            float var = wsum(d0 * d0 + d1 * d1) * (1.f / 64.f);
            float rstd = rsqrtf(var + 1e-5f);
            float2 gg = *(const float2*)&sm->lng[lane * 2];
            float2 bb = *(const float2*)&sm->lnb[lane * 2];
            float2 o;
            o.x = fmaf(d0 * rstd, gg.x, bb.x);
            o.y = fmaf(d1 * rstd, gg.y, bb.y);
            *(float2*)&sm->H[v * HID + lane * 2] = o;
        }
    }
    __syncthreads();

    // ---- GAT layers 1 & 2 ----
    gat_layer(sm, Wg1, as1, ad1, bg1, tid, wid, lane);
    gat_layer(sm, Wg2, as2, ad2, bg2, tid, wid, lane);

    // ---- write final features ----
    const float4* Hv = (const float4*)sm->H;
    float4* outp = (float4*)(g_h + (size_t)g * NPG * HID);
    for (int i = tid; i < NPG * HID / 4; i += GT) outp[i] = Hv[i];
}

// ---- kernel 2: split-K GEMM  partials[ky] = h[1024,8192(slice)] @ W1, FFMA2 inner ----
__global__ void __launch_bounds__(256) head_gemm(const float* __restrict__ W1)
{
    __shared__ float As[64][16];
    __shared__ float Bs[16][128];
    int m0 = blockIdx.x * 64;
    int ky = blockIdx.y;
    int kbase = ky * (8192 / KSPLIT);
    int tid = threadIdx.x;
    int tx = tid & 15, ty = tid >> 4;
    int r0 = ty * 4, c0 = tx * 8;
    ull acc[4][4];
#pragma unroll
    for (int r = 0; r < 4; r++)
#pragma unroll
        for (int c = 0; c < 4; c++) acc[r][c] = 0ull;

    int ar = tid >> 2, aq = (tid & 3) * 4;
    int brr = tid >> 4, bc = (tid & 15) * 8;
    for (int kk = kbase; kk < kbase + 8192 / KSPLIT; kk += 16) {
        *(float4*)&As[ar][aq]      = *(const float4*)&g_h[(size_t)(m0 + ar) * 8192 + kk + aq];
        *(float4*)&Bs[brr][bc]     = *(const float4*)&W1[(size_t)(kk + brr) * 128 + bc];
        *(float4*)&Bs[brr][bc + 4] = *(const float4*)&W1[(size_t)(kk + brr) * 128 + bc + 4];
        __syncthreads();
#pragma unroll
        for (int k = 0; k < 16; k++) {
            ull a0 = pk1(As[r0][k]),     a1 = pk1(As[r0 + 1][k]);
            ull a2 = pk1(As[r0 + 2][k]), a3 = pk1(As[r0 + 3][k]);
            ull b0 = *(const ull*)&Bs[k][c0];
            ull b1 = *(const ull*)&Bs[k][c0 + 2];
            ull b2 = *(const ull*)&Bs[k][c0 + 4];
            ull b3 = *(const ull*)&Bs[k][c0 + 6];
            fma2(acc[0][0], a0, b0); fma2(acc[0][1], a0, b1); fma2(acc[0][2], a0, b2); fma2(acc[0][3], a0, b3);
            fma2(acc[1][0], a1, b0); fma2(acc[1][1], a1, b1); fma2(acc[1][2], a1, b2); fma2(acc[1][3], a1, b3);
            fma2(acc[2][0], a2, b0); fma2(acc[2][1], a2, b1); fma2(acc[2][2], a2, b2); fma2(acc[2][3], a2, b3);
            fma2(acc[3][0], a3, b0); fma2(acc[3][1], a3, b1); fma2(acc[3][2], a3, b2); fma2(acc[3][3], a3, b3);
        }
        __syncthreads();
    }
    float* outp = g_hp[ky];
#pragma unroll
    for (int r = 0; r < 4; r++)
#pragma unroll
        for (int c = 0; c < 4; c++)
            *(ull*)&outp[(m0 + r0 + r) * 128 + c0 + 2 * c] = acc[r][c];
}

// ---- kernel 3: reduce partials + bias, lrelu, @W2, sigmoid; one warp per graph ----
__global__ void head_final(const float* __restrict__ W2, const float* __restrict__ b2,
                           const float* __restrict__ b1, float* __restrict__ outp)
{
    int g = blockIdx.x * 8 + (threadIdx.x >> 5);
    int lane = threadIdx.x & 31;
    float4 s = make_float4(0.f, 0.f, 0.f, 0.f);
#pragma unroll
    for (int ky = 0; ky < KSPLIT; ky++) {
        float4 p = *(const float4*)&g_hp[ky][(size_t)g * 128 + lane * 4];
        s.x += p.x; s.y += p.y; s.z += p.z; s.w += p.w;
    }
    float4 bb = *(const float4*)&b1[lane * 4];
    s.x += bb.x; s.y += bb.y; s.z += bb.z; s.w += bb.w;
    s.x = fmaf(0.495f, fabsf(s.x), 0.505f * s.x);
    s.y = fmaf(0.495f, fabsf(s.y), 0.505f * s.y);
    s.z = fmaf(0.495f, fabsf(s.z), 0.505f * s.z);
    s.w = fmaf(0.495f, fabsf(s.w), 0.505f * s.w);
    float4 w = *(const float4*)&W2[lane * 4];
    float p = s.x * w.x + s.y * w.y + s.z * w.z + s.w * w.w;
    p = wsum(p);
    if (lane == 0) outp[g] = 1.f / (1.f + expf(-(p + b2[0])));
}

extern "C" void kernel_launch(void* const* d_in, const int* in_sizes, int n_in,
                              void* d_out, int out_size)
{
    const float* x    = (const float*)d_in[0];
    const int*   ei   = (const int*)  d_in[1];
    const float* Wl   = (const float*)d_in[2];
    const float* bl   = (const float*)d_in[3];
    const float* Wr   = (const float*)d_in[4];
    const float* br   = (const float*)d_in[5];
    const float* attv = (const float*)d_in[6];
    const float* bv2  = (const float*)d_in[7];
    const float* Wg1  = (const float*)d_in[8];
    const float* as1  = (const float*)d_in[9];
    const float* ad1  = (const float*)d_in[10];
    const float* bg1  = (const float*)d_in[11];
    const float* Wg2  = (const float*)d_in[12];
    const float* as2  = (const float*)d_in[13];
    const float* ad2  = (const float*)d_in[14];
    const float* bg2  = (const float*)d_in[15];
    const float* lng  = (const float*)d_in[16];
    const float* lnb  = (const float*)d_in[17];
    const float* W1   = (const float*)d_in[18];
    const float* b1   = (const float*)d_in[19];
    const float* W2   = (const float*)d_in[20];
    const float* b2   = (const float*)d_in[21];
    float* outp = (float*)d_out;

    int smem = (int)sizeof(SM);
    cudaFuncSetAttribute(gnn_kernel, cudaFuncAttributeMaxDynamicSharedMemorySize, smem);

    gnn_kernel<<<NGRAPH, GT, smem>>>(x, ei, Wl, bl, Wr, br, attv, bv2,
                                     Wg1, as1, ad1, bg1, Wg2, as2, ad2, bg2, lng, lnb);
    head_gemm<<<dim3(16, KSPLIT), 256>>>(W1);
    head_final<<<NGRAPH / 8, 256>>>(W2, b2, b1, outp);
}

// round 13
// speedup vs baseline: 1.0451x; 1.0042x over previous
#include <cuda_runtime.h>

#define NGRAPH 1024
#define NPG    128
#define HID    64
#define EPG    2048            // edges per graph (NPG*16)
#define GT     512             // threads in GNN kernel
#define NW     (GT/32)         // 16 warps
#define KSPLIT 32              // head gemm k-splits

typedef unsigned long long ull;

// ---- f32x2 packed-FMA helpers ----
__device__ __forceinline__ ull pk1(float x) {
    ull r; asm("mov.b64 %0,{%1,%1};" : "=l"(r) : "f"(x)); return r;
}
__device__ __forceinline__ void fma2(ull& d, ull a, ull b) {
    asm("fma.rn.f32x2 %0,%1,%2,%0;" : "+l"(d) : "l"(a), "l"(b));
}
__device__ __forceinline__ float2 unpk(ull v) {
    float2 r; asm("mov.b64 {%0,%1},%2;" : "=f"(r.x), "=f"(r.y) : "l"(v)); return r;
}

// ---- global scratch ----
__device__ float g_h [(size_t)NGRAPH * NPG * HID];        // final node features [1024x8192]
__device__ float g_hp[KSPLIT][(size_t)NGRAPH * 128];      // head GEMM k-split partials

// ---- shared memory (~108.6KB -> 2 CTAs/SM) ----
struct SM {
    float  H[NPG * HID];       // 32KB node features (also xr in GATv2)
    float  A[NPG * HID];       // 32KB xl / xw
    float  W[HID * HID];       // 16KB weight tile
    float2 ae[EPG];            // 16KB CSR-ordered {exp(logit), src byte offset}
    float  xin[NPG * 4];       //  2KB
    float  vec0[HID], vec1[HID], vec2[HID], vec3[HID];
    float  lng[HID], lnb[HID];
    float  alS[NPG], alD[NPG], alE[NPG];
    int    off[NPG + 1];
    int    cnt[NPG];
    int    scanw[4];
    unsigned short csd[EPG];   // 4KB CSR-ordered packed (s | d<<8)
};

__device__ __forceinline__ float wsum(float v) {
#pragma unroll
    for (int o = 16; o; o >>= 1) v += __shfl_xor_sync(0xffffffffu, v, o);
    return v;
}

// CSR-run aggregate: acc += sum_j exp_j * A[src_j], ps += sum_j exp_j.
__device__ __forceinline__ void seg_aggregate(const SM* sm, const char* Ab,
                                              int o0, int o1, ull& acc, float& ps)
{
    int j = o0;
    if (j < o1 && (j & 1)) {
        float2 t = sm->ae[j];
        fma2(acc, pk1(t.x), *(const ull*)(Ab + __float_as_int(t.y)));
        ps += t.x; j++;
    }
    for (; j + 1 < o1; j += 2) {
        float4 t2 = *(const float4*)&sm->ae[j];
        fma2(acc, pk1(t2.x), *(const ull*)(Ab + __float_as_int(t2.y)));
        fma2(acc, pk1(t2.z), *(const ull*)(Ab + __float_as_int(t2.w)));
        ps += t2.x + t2.z;
    }
    if (j < o1) {
        float2 t = sm->ae[j];
        fma2(acc, pk1(t.x), *(const ull*)(Ab + __float_as_int(t.y)));
        ps += t.x;
    }
}

// 64x64 GEMM (A = H @ W) with fused attention-scalar epilogue.
__device__ __forceinline__ void gemm64_att(SM* sm, int wid, int lane)
{
    int r0 = wid * 8;
    ull acc[8];
#pragma unroll
    for (int r = 0; r < 8; r++) acc[r] = 0ull;
    const float* Wb = sm->W + lane * 2;
#pragma unroll 2
    for (int k = 0; k < HID; k += 4) {
        ull w0 = *(const ull*)&Wb[(k + 0) * HID];
        ull w1 = *(const ull*)&Wb[(k + 1) * HID];
        ull w2 = *(const ull*)&Wb[(k + 2) * HID];
        ull w3 = *(const ull*)&Wb[(k + 3) * HID];
#pragma unroll
        for (int r = 0; r < 8; r++) {
            float4 h = *(const float4*)&sm->H[(r0 + r) * HID + k];
            fma2(acc[r], pk1(h.x), w0);
            fma2(acc[r], pk1(h.y), w1);
            fma2(acc[r], pk1(h.z), w2);
            fma2(acc[r], pk1(h.w), w3);
        }
    }
    float2 s2 = *(const float2*)&sm->vec0[lane * 2];
    float2 d2 = *(const float2*)&sm->vec1[lane * 2];
    float ps[8], pd[8];
#pragma unroll
    for (int r = 0; r < 8; r++) {
        *(ull*)&sm->A[(r0 + r) * HID + lane * 2] = acc[r];
        float2 a = unpk(acc[r]);
        ps[r] = a.x * s2.x + a.y * s2.y;
        pd[r] = a.x * d2.x + a.y * d2.y;
    }
#pragma unroll
    for (int o = 16; o; o >>= 1) {
#pragma unroll
        for (int r = 0; r < 8; r++) {
            ps[r] += __shfl_xor_sync(0xffffffffu, ps[r], o);
            pd[r] += __shfl_xor_sync(0xffffffffu, pd[r], o);
        }
    }
    if (lane < 8) {
        int v = r0 + lane;
        float a = ps[lane], b = pd[lane];
        sm->alS[v] = a;
        sm->alD[v] = b;
        float t = a + b;
        sm->alE[v] = __expf(fmaf(0.4f, fabsf(t), 0.6f * t));   // exp(lrelu(t,0.2))
    }
}

// ---- one GATConv layer (with self-loops), fully in SMEM ----
__device__ void gat_layer(SM* sm, const float* __restrict__ Wg,
                          const float* __restrict__ as_, const float* __restrict__ ad_,
                          const float* __restrict__ bias,
                          int tid, int wid, int lane)
{
    for (int i = tid; i < HID * HID; i += GT) sm->W[i] = Wg[i];
    if (tid < HID) { sm->vec0[tid] = as_[tid]; sm->vec1[tid] = ad_[tid]; sm->vec2[tid] = bias[tid]; }
    __syncthreads();

    gemm64_att(sm, wid, lane);     // A = H @ W, plus alS/alD/alE
    __syncthreads();

    // fused logit+exp pass (edge-parallel); one LDS.16 gives both s and d
#pragma unroll
    for (int i = tid; i < EPG; i += GT) {
        int sd = sm->csd[i];
        int s = sd & 255, d = sd >> 8;
        float t = sm->alS[s] + sm->alD[d];
        float2 w;
        w.x = __expf(fmaf(0.4f, fabsf(t), 0.6f * t));
        w.y = __int_as_float(s << 8);
        sm->ae[i] = w;
    }
    __syncthreads();

    // single-pass aggregate + normalize (warp per destination)
    const char* Ab = (const char*)sm->A + lane * 8;
    for (int v = wid; v < NPG; v += NW) {
        ull acc = 0ull; float ps = 0.f;
        seg_aggregate(sm, Ab, sm->off[v], sm->off[v + 1], acc, ps);
        float el = sm->alE[v];
        fma2(acc, pk1(el), *(const ull*)(Ab + (v << 8)));
        float inv = __fdividef(1.f, ps + el + 1e-16f);
        float2 r  = unpk(acc);
        float2 b2 = *(const float2*)&sm->vec2[lane * 2];
        float2 o;
        o.x = fmaxf(fmaf(r.x, inv, b2.x), 0.f);
        o.y = fmaxf(fmaf(r.y, inv, b2.y), 0.f);
        *(float2*)&sm->H[v * HID + lane * 2] = o;
    }
    __syncthreads();
}

// ---- kernel 1: full 3-layer GNN, one CTA per graph, 2 CTAs/SM ----
__global__ void __launch_bounds__(GT, 2) gnn_kernel(
    const float* __restrict__ x, const int* __restrict__ ei,
    const float* __restrict__ Wl, const float* __restrict__ bl,
    const float* __restrict__ Wr, const float* __restrict__ br,
    const float* __restrict__ attv, const float* __restrict__ bv2,
    const float* __restrict__ Wg1, const float* __restrict__ as1,
    const float* __restrict__ ad1, const float* __restrict__ bg1,
    const float* __restrict__ Wg2, const float* __restrict__ as2,
    const float* __restrict__ ad2, const float* __restrict__ bg2,
    const float* __restrict__ lngp, const float* __restrict__ lnbp)
{
    extern __shared__ char smraw[];
    SM* sm = (SM*)smraw;
    int tid = threadIdx.x, lane = tid & 31, wid = tid >> 5;
    int g = blockIdx.x, base = g * NPG;
    const int* srcp = ei + (size_t)g * EPG;
    const int* dstp = ei + (size_t)NGRAPH * EPG + (size_t)g * EPG;

    // ---- load inputs, count in-degrees ----
    for (int i = tid; i < NPG * 4; i += GT) sm->xin[i] = x[(size_t)base * 4 + i];
    if (tid < HID) { sm->lng[tid] = lngp[tid]; sm->lnb[tid] = lnbp[tid]; }
    for (int i = tid; i < NPG; i += GT) sm->cnt[i] = 0;
    __syncthreads();
    for (int i = tid; i < EPG; i += GT) atomicAdd(&sm->cnt[dstp[i] - base], 1);
    __syncthreads();

    // exclusive scan of counts -> off
    int myv = 0, sc = 0;
    if (tid < NPG) {
        myv = sm->cnt[tid]; sc = myv;
#pragma unroll
        for (int o = 1; o < 32; o <<= 1) {
            int n = __shfl_up_sync(0xffffffffu, sc, o);
            if (lane >= o) sc += n;
        }
        if (lane == 31) sm->scanw[wid] = sc;
    }
    __syncthreads();
    if (tid < NPG) {
        int add = 0;
        for (int i = 0; i < wid; i++) add += sm->scanw[i];
        sm->off[tid] = add + sc - myv;
    }
    if (tid == 0) sm->off[NPG] = EPG;
    __syncthreads();
    if (tid < NPG) sm->cnt[tid] = sm->off[tid];
    __syncthreads();
    // scatter into materialized CSR: single u16 store per edge
    for (int i = tid; i < EPG; i += GT) {
        int s = srcp[i] - base, d = dstp[i] - base;
        int pos = atomicAdd(&sm->cnt[d], 1);
        sm->csd[pos] = (unsigned short)(s | (d << 8));
    }

    // ---- GATv2 layer ----
    for (int i = tid; i < 4 * HID; i += GT) { sm->W[i] = Wl[i]; sm->W[4 * HID + i] = Wr[i]; }
    if (tid < HID) { sm->vec0[tid] = bl[tid]; sm->vec1[tid] = br[tid];
                     sm->vec2[tid] = attv[tid]; sm->vec3[tid] = bv2[tid]; }
    __syncthreads();
    {   // xl -> A, xr -> H  (IN = 4, tiny)
        int k = tid & (HID - 1), vg = tid >> 6;
#pragma unroll 4
        for (int r = 0; r < 16; r++) {
            int v = vg * 16 + r;
            float a = sm->vec0[k], b = sm->vec1[k];
#pragma unroll
            for (int i = 0; i < 4; i++) {
                float xv = sm->xin[v * 4 + i];
                a = fmaf(xv, sm->W[i * HID + k], a);
                b = fmaf(xv, sm->W[4 * HID + i * HID + k], b);
            }
            sm->A[v * HID + k] = a;
            sm->H[v * HID + k] = b;
        }
    }
    __syncthreads();
    // v2 logits fused with exp: half-warp per edge (edge-parallel).
    {
        int hl = lane & 15;
        float4 at = *(const float4*)&sm->vec2[hl * 4];
#pragma unroll 2
        for (int j = wid * 2 + (lane >> 4); j < EPG; j += NW * 2) {
            int sd = sm->csd[j];
            int s = sd & 255, d = sd >> 8;
            float4 xl = *(const float4*)&sm->A[s * HID + hl * 4];
            float4 xr = *(const float4*)&sm->H[d * HID + hl * 4];
            float s0 = xl.x + xr.x, s1 = xl.y + xr.y;
            float s2 = xl.z + xr.z, s3 = xl.w + xr.w;
            float p = fmaf(s0, at.x, fmaf(s1, at.y, fmaf(s2, at.z, s3 * at.w)));
            float q = fmaf(fabsf(s0), at.x, fmaf(fabsf(s1), at.y,
                      fmaf(fabsf(s2), at.z, fabsf(s3) * at.w)));
            float t = fmaf(0.4f, q, 0.6f * p);
#pragma unroll
            for (int o = 8; o; o >>= 1) t += __shfl_xor_sync(0xffffffffu, t, o);
            if (hl == 0)
                sm->ae[j] = make_float2(__expf(t), __int_as_float(s << 8));
        }
    }
    __syncthreads();
    // aggregate + bias + lrelu(0.01) + layernorm -> H   (no self-loop in GATv2)
    {
        const char* Ab = (const char*)sm->A + lane * 8;
        for (int v = wid; v < NPG; v += NW) {
            ull acc = 0ull; float ps = 0.f;
            seg_aggregate(sm, Ab, sm->off[v], sm->off[v + 1], acc, ps);
            float inv = __fdividef(1.f, ps + 1e-16f);
            float2 r  = unpk(acc);
            float2 b2 = *(const float2*)&sm->vec3[lane * 2];
            float u0 = fmaf(r.x, inv, b2.x);
            float u1 = fmaf(r.y, inv, b2.y);
            float t0 = fmaf(0.495f, fabsf(u0), 0.505f * u0);   // lrelu 0.01
            float t1 = fmaf(0.495f, fabsf(u1), 0.505f * u1);
            float mean = wsum(t0 + t1) * (1.f / 64.f);
            float d0 = t0 - mean, d1 = t1 - mean;
            float var = wsum(d0 * d0 + d1 * d1) * (1.f / 64.f);
            float rstd = rsqrtf(var + 1e-5f);
            float2 gg = *(const float2*)&sm->lng[lane * 2];
            float2 bb = *(const float2*)&sm->lnb[lane * 2];
            float2 o;
            o.x = fmaf(d0 * rstd, gg.x, bb.x);
            o.y = fmaf(d1 * rstd, gg.y, bb.y);
            *(float2*)&sm->H[v * HID + lane * 2] = o;
        }
    }
    __syncthreads();

    // ---- GAT layers 1 & 2 ----
    gat_layer(sm, Wg1, as1, ad1, bg1, tid, wid, lane);
    gat_layer(sm, Wg2, as2, ad2, bg2, tid, wid, lane);

    // ---- write final features ----
    const float4* Hv = (const float4*)sm->H;
    float4* outp = (float4*)(g_h + (size_t)g * NPG * HID);
    for (int i = tid; i < NPG * HID / 4; i += GT) outp[i] = Hv[i];
}

// ---- kernel 2: split-K GEMM, double-buffered, conflict-free B loads ----
__global__ void __launch_bounds__(256) head_gemm(const float* __restrict__ W1)
{
    __shared__ float As[2][64][16];
    __shared__ float Bs[2][16][128];
    int m0 = blockIdx.x * 64;
    int kbase = blockIdx.y * (8192 / KSPLIT);   // 256 k per CTA, 16 chunks of 16
    int tid = threadIdx.x;
    int tx = tid & 15, ty = tid >> 4;
    int r0 = ty * 4, c0 = tx * 8;
    int ar = tid >> 2, aq = (tid & 3) * 4;
    int brr = tid >> 4, bc = (tid & 15) * 8;

    const float* gA = &g_h[(size_t)(m0 + ar) * 8192 + kbase + aq];
    const float* gB = &W1[(size_t)(kbase + brr) * 128 + bc];

    ull acc[4][4];
#pragma unroll
    for (int r = 0; r < 4; r++)
#pragma unroll
        for (int c = 0; c < 4; c++) acc[r][c] = 0ull;

    // prologue: fetch chunk 0
    float4 pa  = *(const float4*)gA;
    float4 pb0 = *(const float4*)gB;
    float4 pb1 = *(const float4*)(gB + 4);

#pragma unroll 1
    for (int ch = 0; ch < 16; ch++) {
        int buf = ch & 1;
        *(float4*)&As[buf][ar][aq]     = pa;
        *(float4*)&Bs[buf][brr][bc]     = pb0;
        *(float4*)&Bs[buf][brr][bc + 4] = pb1;
        __syncthreads();
        if (ch + 1 < 16) {   // prefetch next chunk while computing this one
            pa  = *(const float4*)(gA + (ch + 1) * 16);
            pb0 = *(const float4*)(gB + (size_t)(ch + 1) * 2048);
            pb1 = *(const float4*)(gB + (size_t)(ch + 1) * 2048 + 4);
        }
#pragma unroll
        for (int k = 0; k < 16; k++) {
            ull a0 = pk1(As[buf][r0][k]),     a1 = pk1(As[buf][r0 + 1][k]);
            ull a2 = pk1(As[buf][r0 + 2][k]), a3 = pk1(As[buf][r0 + 3][k]);
            ulonglong2 bA = *(const ulonglong2*)&Bs[buf][k][c0];       // conflict-free
            ulonglong2 bB = *(const ulonglong2*)&Bs[buf][k][c0 + 4];
            fma2(acc[0][0], a0, bA.x); fma2(acc[0][1], a0, bA.y); fma2(acc[0][2], a0, bB.x); fma2(acc[0][3], a0, bB.y);
            fma2(acc[1][0], a1, bA.x); fma2(acc[1][1], a1, bA.y); fma2(acc[1][2], a1, bB.x); fma2(acc[1][3], a1, bB.y);
            fma2(acc[2][0], a2, bA.x); fma2(acc[2][1], a2, bA.y); fma2(acc[2][2], a2, bB.x); fma2(acc[2][3], a2, bB.y);
            fma2(acc[3][0], a3, bA.x); fma2(acc[3][1], a3, bA.y); fma2(acc[3][2], a3, bB.x); fma2(acc[3][3], a3, bB.y);
        }
        __syncthreads();
    }
    float* outp = g_hp[blockIdx.y];
#pragma unroll
    for (int r = 0; r < 4; r++)
#pragma unroll
        for (int c = 0; c < 4; c++)
            *(ull*)&outp[(m0 + r0 + r) * 128 + c0 + 2 * c] = acc[r][c];
}

// ---- kernel 3: reduce partials + bias, lrelu, @W2, sigmoid; one warp per graph ----
__global__ void head_final(const float* __restrict__ W2, const float* __restrict__ b2,
                           const float* __restrict__ b1, float* __restrict__ outp)
{
    int g = blockIdx.x * 8 + (threadIdx.x >> 5);
    int lane = threadIdx.x & 31;
    float4 s = make_float4(0.f, 0.f, 0.f, 0.f);
#pragma unroll
    for (int ky = 0; ky < KSPLIT; ky++) {
        float4 p = *(const float4*)&g_hp[ky][(size_t)g * 128 + lane * 4];
        s.x += p.x; s.y += p.y; s.z += p.z; s.w += p.w;
    }
    float4 bb = *(const float4*)&b1[lane * 4];
    s.x += bb.x; s.y += bb.y; s.z += bb.z; s.w += bb.w;
    s.x = fmaf(0.495f, fabsf(s.x), 0.505f * s.x);
    s.y = fmaf(0.495f, fabsf(s.y), 0.505f * s.y);
    s.z = fmaf(0.495f, fabsf(s.z), 0.505f * s.z);
    s.w = fmaf(0.495f, fabsf(s.w), 0.505f * s.w);
    float4 w = *(const float4*)&W2[lane * 4];
    float p = s.x * w.x + s.y * w.y + s.z * w.z + s.w * w.w;
    p = wsum(p);
    if (lane == 0) outp[g] = 1.f / (1.f + expf(-(p + b2[0])));
}

extern "C" void kernel_launch(void* const* d_in, const int* in_sizes, int n_in,
                              void* d_out, int out_size)
{
    const float* x    = (const float*)d_in[0];
    const int*   ei   = (const int*)  d_in[1];
    const float* Wl   = (const float*)d_in[2];
    const float* bl   = (const float*)d_in[3];
    const float* Wr   = (const float*)d_in[4];
    const float* br   = (const float*)d_in[5];
    const float* attv = (const float*)d_in[6];
    const float* bv2  = (const float*)d_in[7];
    const float* Wg1  = (const float*)d_in[8];
    const float* as1  = (const float*)d_in[9];
    const float* ad1  = (const float*)d_in[10];
    const float* bg1  = (const float*)d_in[11];
    const float* Wg2  = (const float*)d_in[12];
    const float* as2  = (const float*)d_in[13];
    const float* ad2  = (const float*)d_in[14];
    const float* bg2  = (const float*)d_in[15];
    const float* lng  = (const float*)d_in[16];
    const float* lnb  = (const float*)d_in[17];
    const float* W1   = (const float*)d_in[18];
    const float* b1   = (const float*)d_in[19];
    const float* W2   = (const float*)d_in[20];
    const float* b2   = (const float*)d_in[21];
    float* outp = (float*)d_out;

    int smem = (int)sizeof(SM);
    cudaFuncSetAttribute(gnn_kernel, cudaFuncAttributeMaxDynamicSharedMemorySize, smem);

    gnn_kernel<<<NGRAPH, GT, smem>>>(x, ei, Wl, bl, Wr, br, attv, bv2,
                                     Wg1, as1, ad1, bg1, Wg2, as2, ad2, bg2, lng, lnb);
    head_gemm<<<dim3(16, KSPLIT), 256>>>(W1);
    head_final<<<NGRAPH / 8, 256>>>(W2, b2, b1, outp);
}

// round 14
// speedup vs baseline: 1.1145x; 1.0664x over previous
#include <cuda_runtime.h>

#define NGRAPH 1024
#define NPG    128
#define HID    64
#define EPG    2048            // edges per graph (NPG*16)
#define GT     512             // threads in GNN kernel
#define NW     (GT/32)         // 16 warps
#define KSPLIT 32              // head gemm k-splits

typedef unsigned long long ull;

// ---- f32x2 packed-FMA helpers ----
__device__ __forceinline__ ull pk1(float x) {
    ull r; asm("mov.b64 %0,{%1,%1};" : "=l"(r) : "f"(x)); return r;
}
__device__ __forceinline__ void fma2(ull& d, ull a, ull b) {
    asm("fma.rn.f32x2 %0,%1,%2,%0;" : "+l"(d) : "l"(a), "l"(b));
}
__device__ __forceinline__ float2 unpk(ull v) {
    float2 r; asm("mov.b64 {%0,%1},%2;" : "=f"(r.x), "=f"(r.y) : "l"(v)); return r;
}

// ---- global scratch ----
__device__ float g_h [(size_t)NGRAPH * NPG * HID];        // final node features [1024x8192]
__device__ float g_hp[KSPLIT][(size_t)NGRAPH * 128];      // head GEMM k-split partials

// ---- shared memory (~108.6KB -> 2 CTAs/SM) ----
struct SM {
    float  H[NPG * HID];       // 32KB node features (also xr in GATv2)
    float  A[NPG * HID];       // 32KB xl / xw
    float  W[HID * HID];       // 16KB weight tile
    float2 ae[EPG];            // 16KB CSR-ordered {exp(logit), src byte offset}
    float  xin[NPG * 4];       //  2KB
    float  vec0[HID], vec1[HID], vec2[HID], vec3[HID];
    float  lng[HID], lnb[HID];
    float  alS[NPG], alD[NPG], alE[NPG];
    int    off[NPG + 1];
    int    cnt[NPG];
    int    scanw[4];
    unsigned short csd[EPG];   // 4KB CSR-ordered packed (s | d<<8)
};

__device__ __forceinline__ float wsum(float v) {
#pragma unroll
    for (int o = 16; o; o >>= 1) v += __shfl_xor_sync(0xffffffffu, v, o);
    return v;
}

// CSR-run aggregate: acc += sum_j exp_j * A[src_j], ps += sum_j exp_j.
__device__ __forceinline__ void seg_aggregate(const SM* sm, const char* Ab,
                                              int o0, int o1, ull& acc, float& ps)
{
    int j = o0;
    if (j < o1 && (j & 1)) {
        float2 t = sm->ae[j];
        fma2(acc, pk1(t.x), *(const ull*)(Ab + __float_as_int(t.y)));
        ps += t.x; j++;
    }
    for (; j + 1 < o1; j += 2) {
        float4 t2 = *(const float4*)&sm->ae[j];
        fma2(acc, pk1(t2.x), *(const ull*)(Ab + __float_as_int(t2.y)));
        fma2(acc, pk1(t2.z), *(const ull*)(Ab + __float_as_int(t2.w)));
        ps += t2.x + t2.z;
    }
    if (j < o1) {
        float2 t = sm->ae[j];
        fma2(acc, pk1(t.x), *(const ull*)(Ab + __float_as_int(t.y)));
        ps += t.x;
    }
}

// 64x64 GEMM (A = H @ W) with fused attention-scalar epilogue.
__device__ __forceinline__ void gemm64_att(SM* sm, int wid, int lane)
{
    int r0 = wid * 8;
    ull acc[8];
#pragma unroll
    for (int r = 0; r < 8; r++) acc[r] = 0ull;
    const float* Wb = sm->W + lane * 2;
#pragma unroll 2
    for (int k = 0; k < HID; k += 4) {
        ull w0 = *(const ull*)&Wb[(k + 0) * HID];
        ull w1 = *(const ull*)&Wb[(k + 1) * HID];
        ull w2 = *(const ull*)&Wb[(k + 2) * HID];
        ull w3 = *(const ull*)&Wb[(k + 3) * HID];
#pragma unroll
        for (int r = 0; r < 8; r++) {
            float4 h = *(const float4*)&sm->H[(r0 + r) * HID + k];
            fma2(acc[r], pk1(h.x), w0);
            fma2(acc[r], pk1(h.y), w1);
            fma2(acc[r], pk1(h.z), w2);
            fma2(acc[r], pk1(h.w), w3);
        }
    }
    float2 s2 = *(const float2*)&sm->vec0[lane * 2];
    float2 d2 = *(const float2*)&sm->vec1[lane * 2];
    float ps[8], pd[8];
#pragma unroll
    for (int r = 0; r < 8; r++) {
        *(ull*)&sm->A[(r0 + r) * HID + lane * 2] = acc[r];
        float2 a = unpk(acc[r]);
        ps[r] = a.x * s2.x + a.y * s2.y;
        pd[r] = a.x * d2.x + a.y * d2.y;
    }
#pragma unroll
    for (int o = 16; o; o >>= 1) {
#pragma unroll
        for (int r = 0; r < 8; r++) {
            ps[r] += __shfl_xor_sync(0xffffffffu, ps[r], o);
            pd[r] += __shfl_xor_sync(0xffffffffu, pd[r], o);
        }
    }
    if (lane < 8) {
        int v = r0 + lane;
        float a = ps[lane], b = pd[lane];
        sm->alS[v] = a;
        sm->alD[v] = b;
        float t = a + b;
        sm->alE[v] = __expf(fmaf(0.4f, fabsf(t), 0.6f * t));   // exp(lrelu(t,0.2))
    }
}

// ---- one GATConv layer (with self-loops), fully in SMEM ----
__device__ void gat_layer(SM* sm, const float* __restrict__ Wg,
                          const float* __restrict__ as_, const float* __restrict__ ad_,
                          const float* __restrict__ bias,
                          int tid, int wid, int lane)
{
    for (int i = tid; i < HID * HID; i += GT) sm->W[i] = Wg[i];
    if (tid < HID) { sm->vec0[tid] = as_[tid]; sm->vec1[tid] = ad_[tid]; sm->vec2[tid] = bias[tid]; }
    __syncthreads();

    gemm64_att(sm, wid, lane);     // A = H @ W, plus alS/alD/alE
    __syncthreads();

    // fused logit+exp pass (edge-parallel); one LDS.16 gives both s and d
#pragma unroll
    for (int i = tid; i < EPG; i += GT) {
        int sd = sm->csd[i];
        int s = sd & 255, d = sd >> 8;
        float t = sm->alS[s] + sm->alD[d];
        float2 w;
        w.x = __expf(fmaf(0.4f, fabsf(t), 0.6f * t));
        w.y = __int_as_float(s << 8);
        sm->ae[i] = w;
    }
    __syncthreads();

    // single-pass aggregate + normalize (warp per destination)
    const char* Ab = (const char*)sm->A + lane * 8;
    for (int v = wid; v < NPG; v += NW) {
        ull acc = 0ull; float ps = 0.f;
        seg_aggregate(sm, Ab, sm->off[v], sm->off[v + 1], acc, ps);
        float el = sm->alE[v];
        fma2(acc, pk1(el), *(const ull*)(Ab + (v << 8)));
        float inv = __fdividef(1.f, ps + el + 1e-16f);
        float2 r  = unpk(acc);
        float2 b2 = *(const float2*)&sm->vec2[lane * 2];
        float2 o;
        o.x = fmaxf(fmaf(r.x, inv, b2.x), 0.f);
        o.y = fmaxf(fmaf(r.y, inv, b2.y), 0.f);
        *(float2*)&sm->H[v * HID + lane * 2] = o;
    }
    __syncthreads();
}

// ---- kernel 1: full 3-layer GNN, one CTA per graph, 2 CTAs/SM ----
__global__ void __launch_bounds__(GT, 2) gnn_kernel(
    const float* __restrict__ x, const int* __restrict__ ei,
    const float* __restrict__ Wl, const float* __restrict__ bl,
    const float* __restrict__ Wr, const float* __restrict__ br,
    const float* __restrict__ attv, const float* __restrict__ bv2,
    const float* __restrict__ Wg1, const float* __restrict__ as1,
    const float* __restrict__ ad1, const float* __restrict__ bg1,
    const float* __restrict__ Wg2, const float* __restrict__ as2,
    const float* __restrict__ ad2, const float* __restrict__ bg2,
    const float* __restrict__ lngp, const float* __restrict__ lnbp)
{
    extern __shared__ char smraw[];
    SM* sm = (SM*)smraw;
    int tid = threadIdx.x, lane = tid & 31, wid = tid >> 5;
    int g = blockIdx.x, base = g * NPG;
    const int* srcp = ei + (size_t)g * EPG;
    const int* dstp = ei + (size_t)NGRAPH * EPG + (size_t)g * EPG;

    // ---- load inputs, count in-degrees ----
    for (int i = tid; i < NPG * 4; i += GT) sm->xin[i] = x[(size_t)base * 4 + i];
    if (tid < HID) { sm->lng[tid] = lngp[tid]; sm->lnb[tid] = lnbp[tid]; }
    for (int i = tid; i < NPG; i += GT) sm->cnt[i] = 0;
    __syncthreads();
    for (int i = tid; i < EPG; i += GT) atomicAdd(&sm->cnt[dstp[i] - base], 1);
    __syncthreads();

    // exclusive scan of counts -> off
    int myv = 0, sc = 0;
    if (tid < NPG) {
        myv = sm->cnt[tid]; sc = myv;
#pragma unroll
        for (int o = 1; o < 32; o <<= 1) {
            int n = __shfl_up_sync(0xffffffffu, sc, o);
            if (lane >= o) sc += n;
        }
        if (lane == 31) sm->scanw[wid] = sc;
    }
    __syncthreads();
    if (tid < NPG) {
        int add = 0;
        for (int i = 0; i < wid; i++) add += sm->scanw[i];
        sm->off[tid] = add + sc - myv;
    }
    if (tid == 0) sm->off[NPG] = EPG;
    __syncthreads();
    if (tid < NPG) sm->cnt[tid] = sm->off[tid];
    __syncthreads();
    // scatter into materialized CSR: single u16 store per edge
    for (int i = tid; i < EPG; i += GT) {
        int s = srcp[i] - base, d = dstp[i] - base;
        int pos = atomicAdd(&sm->cnt[d], 1);
        sm->csd[pos] = (unsigned short)(s | (d << 8));
    }

    // ---- GATv2 layer ----
    for (int i = tid; i < 4 * HID; i += GT) { sm->W[i] = Wl[i]; sm->W[4 * HID + i] = Wr[i]; }
    if (tid < HID) { sm->vec0[tid] = bl[tid]; sm->vec1[tid] = br[tid];
                     sm->vec2[tid] = attv[tid]; sm->vec3[tid] = bv2[tid]; }
    __syncthreads();
    {   // xl -> A, xr -> H  (IN = 4, tiny)
        int k = tid & (HID - 1), vg = tid >> 6;
#pragma unroll 4
        for (int r = 0; r < 16; r++) {
            int v = vg * 16 + r;
            float a = sm->vec0[k], b = sm->vec1[k];
#pragma unroll
            for (int i = 0; i < 4; i++) {
                float xv = sm->xin[v * 4 + i];
                a = fmaf(xv, sm->W[i * HID + k], a);
                b = fmaf(xv, sm->W[4 * HID + i * HID + k], b);
            }
            sm->A[v * HID + k] = a;
            sm->H[v * HID + k] = b;
        }
    }
    __syncthreads();
    // v2 logits fused with exp: half-warp per edge over CONTIGUOUS per-warp
    // chunks (CSR dst-runs preserved) with xr cached in registers, reloaded
    // only when the destination changes (~1/8 of iterations).
    {
        int hl = lane & 15, half = lane >> 4;
        float4 at = *(const float4*)&sm->vec2[hl * 4];
        int j0 = wid * (EPG / NW);
        int dcur = -1;
        float4 xr = make_float4(0.f, 0.f, 0.f, 0.f);
        for (int jj = j0; jj < j0 + EPG / NW; jj += 2) {
            int j = jj + half;
            int sd = sm->csd[j];
            int s = sd & 255, d = sd >> 8;
            if (d != dcur) {               // predicated, rare
                xr = *(const float4*)&sm->H[d * HID + hl * 4];
                dcur = d;
            }
            float4 xl = *(const float4*)&sm->A[s * HID + hl * 4];
            float s0 = xl.x + xr.x, s1 = xl.y + xr.y;
            float s2 = xl.z + xr.z, s3 = xl.w + xr.w;
            float p = fmaf(s0, at.x, fmaf(s1, at.y, fmaf(s2, at.z, s3 * at.w)));
            float q = fmaf(fabsf(s0), at.x, fmaf(fabsf(s1), at.y,
                      fmaf(fabsf(s2), at.z, fabsf(s3) * at.w)));
            float t = fmaf(0.4f, q, 0.6f * p);
#pragma unroll
            for (int o = 8; o; o >>= 1) t += __shfl_xor_sync(0xffffffffu, t, o);
            if (hl == 0)
                sm->ae[j] = make_float2(__expf(t), __int_as_float(s << 8));
        }
    }
    __syncthreads();
    // aggregate + bias + lrelu(0.01) + layernorm -> H   (no self-loop in GATv2)
    {
        const char* Ab = (const char*)sm->A + lane * 8;
        for (int v = wid; v < NPG; v += NW) {
            ull acc = 0ull; float ps = 0.f;
            seg_aggregate(sm, Ab, sm->off[v], sm->off[v + 1], acc, ps);
            float inv = __fdividef(1.f, ps + 1e-16f);
            float2 r  = unpk(acc);
            float2 b2 = *(const float2*)&sm->vec3[lane * 2];
            float u0 = fmaf(r.x, inv, b2.x);
            float u1 = fmaf(r.y, inv, b2.y);
            float t0 = fmaf(0.495f, fabsf(u0), 0.505f * u0);   // lrelu 0.01
            float t1 = fmaf(0.495f, fabsf(u1), 0.505f * u1);
            float mean = wsum(t0 + t1) * (1.f / 64.f);
            float d0 = t0 - mean, d1 = t1 - mean;
            float var = wsum(d0 * d0 + d1 * d1) * (1.f / 64.f);
            float rstd = rsqrtf(var + 1e-5f);
            float2 gg = *(const float2*)&sm->lng[lane * 2];
            float2 bb = *(const float2*)&sm->lnb[lane * 2];
            float2 o;
            o.x = fmaf(d0 * rstd, gg.x, bb.x);
            o.y = fmaf(d1 * rstd, gg.y, bb.y);
            *(float2*)&sm->H[v * HID + lane * 2] = o;
        }
    }
    __syncthreads();

    // ---- GAT layers 1 & 2 ----
    gat_layer(sm, Wg1, as1, ad1, bg1, tid, wid, lane);
    gat_layer(sm, Wg2, as2, ad2, bg2, tid, wid, lane);

    // ---- write final features ----
    const float4* Hv = (const float4*)sm->H;
    float4* outp = (float4*)(g_h + (size_t)g * NPG * HID);
    for (int i = tid; i < NPG * HID / 4; i += GT) outp[i] = Hv[i];
}

// ---- kernel 2: split-K GEMM, 128 threads, 8x8 thread tile, double-buffered ----
// Per-k per-warp LSU: B 4wf (ty-halves dedup) + A ~0.5wf (float4 k-groups,
// row-group dedup) for 32 FFMA2 -> FMA-bound.
__global__ void __launch_bounds__(128) head_gemm(const float* __restrict__ W1)
{
    __shared__ float As[2][64][20];    // padded: conflict-free transstores, aligned reads
    __shared__ float Bs[2][16][132];
    int m0 = blockIdx.x * 64;
    int kbase = blockIdx.y * 256;
    int tid = threadIdx.x;
    int tx = tid & 15, ty = tid >> 4;          // ty 0..7
    int r0 = ty * 8, c0 = tx * 8;
    int ar = tid >> 1, aq = (tid & 1) * 8;     // A: 2 float4 per thread
    int brr = tid >> 3, bc = (tid & 7) * 16;   // B: 4 float4 per thread

    const float* gA = &g_h[(size_t)(m0 + ar) * 8192 + kbase + aq];
    const float* gB = &W1[(size_t)(kbase + brr) * 128 + bc];

    ull acc[8][4];
#pragma unroll
    for (int r = 0; r < 8; r++)
#pragma unroll
        for (int c = 0; c < 4; c++) acc[r][c] = 0ull;

    // prologue: fetch chunk 0
    float4 pa0 = *(const float4*)gA;
    float4 pa1 = *(const float4*)(gA + 4);
    float4 pb[4];
#pragma unroll
    for (int i = 0; i < 4; i++) pb[i] = *(const float4*)(gB + i * 4);

#pragma unroll 1
    for (int ch = 0; ch < 16; ch++) {
        int buf = ch & 1;
        *(float4*)&As[buf][ar][aq]     = pa0;
        *(float4*)&As[buf][ar][aq + 4] = pa1;
#pragma unroll
        for (int i = 0; i < 4; i++) *(float4*)&Bs[buf][brr][bc + i * 4] = pb[i];
        __syncthreads();
        if (ch + 1 < 16) {
            pa0 = *(const float4*)(gA + (ch + 1) * 16);
            pa1 = *(const float4*)(gA + (ch + 1) * 16 + 4);
#pragma unroll
            for (int i = 0; i < 4; i++)
                pb[i] = *(const float4*)(gB + (size_t)(ch + 1) * 2048 + i * 4);
        }
#pragma unroll
        for (int kg = 0; kg < 4; kg++) {
            float4 a4[8];
#pragma unroll
            for (int r = 0; r < 8; r++)
                a4[r] = *(const float4*)&As[buf][r0 + r][kg * 4];
#pragma unroll
            for (int kk = 0; kk < 4; kk++) {
                int k = kg * 4 + kk;
                ulonglong2 bA = *(const ulonglong2*)&Bs[buf][k][c0];
                ulonglong2 bB = *(const ulonglong2*)&Bs[buf][k][c0 + 4];
#pragma unroll
                for (int r = 0; r < 8; r++) {
                    float av = (kk == 0) ? a4[r].x : (kk == 1) ? a4[r].y
                             : (kk == 2) ? a4[r].z : a4[r].w;
                    ull ap = pk1(av);
                    fma2(acc[r][0], ap, bA.x);
                    fma2(acc[r][1], ap, bA.y);
                    fma2(acc[r][2], ap, bB.x);
                    fma2(acc[r][3], ap, bB.y);
                }
            }
        }
        __syncthreads();
    }
    float* outp = g_hp[blockIdx.y];
#pragma unroll
    for (int r = 0; r < 8; r++)
#pragma unroll
        for (int c = 0; c < 4; c++)
            *(ull*)&outp[(m0 + r0 + r) * 128 + c0 + 2 * c] = acc[r][c];
}

// ---- kernel 3: reduce partials + bias, lrelu, @W2, sigmoid; one warp per graph ----
__global__ void head_final(const float* __restrict__ W2, const float* __restrict__ b2,
                           const float* __restrict__ b1, float* __restrict__ outp)
{
    int g = blockIdx.x * 8 + (threadIdx.x >> 5);
    int lane = threadIdx.x & 31;
    float4 s = make_float4(0.f, 0.f, 0.f, 0.f);
#pragma unroll
    for (int ky = 0; ky < KSPLIT; ky++) {
        float4 p = *(const float4*)&g_hp[ky][(size_t)g * 128 + lane * 4];
        s.x += p.x; s.y += p.y; s.z += p.z; s.w += p.w;
    }
    float4 bb = *(const float4*)&b1[lane * 4];
    s.x += bb.x; s.y += bb.y; s.z += bb.z; s.w += bb.w;
    s.x = fmaf(0.495f, fabsf(s.x), 0.505f * s.x);
    s.y = fmaf(0.495f, fabsf(s.y), 0.505f * s.y);
    s.z = fmaf(0.495f, fabsf(s.z), 0.505f * s.z);
    s.w = fmaf(0.495f, fabsf(s.w), 0.505f * s.w);
    float4 w = *(const float4*)&W2[lane * 4];
    float p = s.x * w.x + s.y * w.y + s.z * w.z + s.w * w.w;
    p = wsum(p);
    if (lane == 0) outp[g] = 1.f / (1.f + expf(-(p + b2[0])));
}

extern "C" void kernel_launch(void* const* d_in, const int* in_sizes, int n_in,
                              void* d_out, int out_size)
{
    const float* x    = (const float*)d_in[0];
    const int*   ei   = (const int*)  d_in[1];
    const float* Wl   = (const float*)d_in[2];
    const float* bl   = (const float*)d_in[3];
    const float* Wr   = (const float*)d_in[4];
    const float* br   = (const float*)d_in[5];
    const float* attv = (const float*)d_in[6];
    const float* bv2  = (const float*)d_in[7];
    const float* Wg1  = (const float*)d_in[8];
    const float* as1  = (const float*)d_in[9];
    const float* ad1  = (const float*)d_in[10];
    const float* bg1  = (const float*)d_in[11];
    const float* Wg2  = (const float*)d_in[12];
    const float* as2  = (const float*)d_in[13];
    const float* ad2  = (const float*)d_in[14];
    const float* bg2  = (const float*)d_in[15];
    const float* lng  = (const float*)d_in[16];
    const float* lnb  = (const float*)d_in[17];
    const float* W1   = (const float*)d_in[18];
    const float* b1   = (const float*)d_in[19];
    const float* W2   = (const float*)d_in[20];
    const float* b2   = (const float*)d_in[21];
    float* outp = (float*)d_out;

    int smem = (int)sizeof(SM);
    cudaFuncSetAttribute(gnn_kernel, cudaFuncAttributeMaxDynamicSharedMemorySize, smem);

    gnn_kernel<<<NGRAPH, GT, smem>>>(x, ei, Wl, bl, Wr, br, attv, bv2,
                                     Wg1, as1, ad1, bg1, Wg2, as2, ad2, bg2, lng, lnb);
    head_gemm<<<dim3(16, KSPLIT), 128>>>(W1);
    head_final<<<NGRAPH / 8, 256>>>(W2, b2, b1, outp);
}

// round 15
// speedup vs baseline: 1.2353x; 1.1083x over previous
#include <cuda_runtime.h>

#define NGRAPH 1024
#define NPG    128
#define HID    64
#define EPG    2048            // edges per graph (NPG*16)
#define GT     512             // threads in GNN kernel
#define NW     (GT/32)         // 16 warps
#define KSPLIT 16              // head gemm k-splits (128 CTAs = 1 wave)

typedef unsigned long long ull;

// ---- f32x2 packed-FMA helpers (gnn kernel) ----
__device__ __forceinline__ ull pk1(float x) {
    ull r; asm("mov.b64 %0,{%1,%1};" : "=l"(r) : "f"(x)); return r;
}
__device__ __forceinline__ void fma2(ull& d, ull a, ull b) {
    asm("fma.rn.f32x2 %0,%1,%2,%0;" : "+l"(d) : "l"(a), "l"(b));
}
__device__ __forceinline__ float2 unpk(ull v) {
    float2 r; asm("mov.b64 {%0,%1},%2;" : "=f"(r.x), "=f"(r.y) : "l"(v)); return r;
}

// ---- tf32 helpers (head gemm) ----
__device__ __forceinline__ unsigned cvt_tf32(float f) {
    unsigned r; asm("cvt.rna.tf32.f32 %0, %1;" : "=r"(r) : "f"(f)); return r;
}
__device__ __forceinline__ void mma_tf32(float* c, const unsigned* a, const unsigned* b) {
    asm("mma.sync.aligned.m16n8k8.row.col.f32.tf32.tf32.f32 "
        "{%0,%1,%2,%3}, {%4,%5,%6,%7}, {%8,%9}, {%0,%1,%2,%3};"
        : "+f"(c[0]), "+f"(c[1]), "+f"(c[2]), "+f"(c[3])
        : "r"(a[0]), "r"(a[1]), "r"(a[2]), "r"(a[3]), "r"(b[0]), "r"(b[1]));
}

// ---- global scratch ----
__device__ float g_h [(size_t)NGRAPH * NPG * HID];        // final node features [1024x8192]
__device__ float g_hp[KSPLIT][(size_t)NGRAPH * 128];      // head GEMM k-split partials

// ---- shared memory (~108.6KB -> 2 CTAs/SM) ----
struct SM {
    float  H[NPG * HID];       // 32KB node features (also xr in GATv2)
    float  A[NPG * HID];       // 32KB xl / xw
    float  W[HID * HID];       // 16KB weight tile
    float2 ae[EPG];            // 16KB CSR-ordered {exp(logit), src byte offset}
    float  xin[NPG * 4];       //  2KB
    float  vec0[HID], vec1[HID], vec2[HID], vec3[HID];
    float  lng[HID], lnb[HID];
    float  alS[NPG], alD[NPG], alE[NPG];
    int    off[NPG + 1];
    int    cnt[NPG];
    int    scanw[4];
    unsigned short csd[EPG];   // 4KB CSR-ordered packed (s | d<<8)
};

__device__ __forceinline__ float wsum(float v) {
#pragma unroll
    for (int o = 16; o; o >>= 1) v += __shfl_xor_sync(0xffffffffu, v, o);
    return v;
}

// CSR-run aggregate: acc += sum_j exp_j * A[src_j], ps += sum_j exp_j.
__device__ __forceinline__ void seg_aggregate(const SM* sm, const char* Ab,
                                              int o0, int o1, ull& acc, float& ps)
{
    int j = o0;
    if (j < o1 && (j & 1)) {
        float2 t = sm->ae[j];
        fma2(acc, pk1(t.x), *(const ull*)(Ab + __float_as_int(t.y)));
        ps += t.x; j++;
    }
    for (; j + 1 < o1; j += 2) {
        float4 t2 = *(const float4*)&sm->ae[j];
        fma2(acc, pk1(t2.x), *(const ull*)(Ab + __float_as_int(t2.y)));
        fma2(acc, pk1(t2.z), *(const ull*)(Ab + __float_as_int(t2.w)));
        ps += t2.x + t2.z;
    }
    if (j < o1) {
        float2 t = sm->ae[j];
        fma2(acc, pk1(t.x), *(const ull*)(Ab + __float_as_int(t.y)));
        ps += t.x;
    }
}

// 64x64 GEMM (A = H @ W) with fused attention-scalar epilogue.
__device__ __forceinline__ void gemm64_att(SM* sm, int wid, int lane)
{
    int r0 = wid * 8;
    ull acc[8];
#pragma unroll
    for (int r = 0; r < 8; r++) acc[r] = 0ull;
    const float* Wb = sm->W + lane * 2;
#pragma unroll 2
    for (int k = 0; k < HID; k += 4) {
        ull w0 = *(const ull*)&Wb[(k + 0) * HID];
        ull w1 = *(const ull*)&Wb[(k + 1) * HID];
        ull w2 = *(const ull*)&Wb[(k + 2) * HID];
        ull w3 = *(const ull*)&Wb[(k + 3) * HID];
#pragma unroll
        for (int r = 0; r < 8; r++) {
            float4 h = *(const float4*)&sm->H[(r0 + r) * HID + k];
            fma2(acc[r], pk1(h.x), w0);
            fma2(acc[r], pk1(h.y), w1);
            fma2(acc[r], pk1(h.z), w2);
            fma2(acc[r], pk1(h.w), w3);
        }
    }
    float2 s2 = *(const float2*)&sm->vec0[lane * 2];
    float2 d2 = *(const float2*)&sm->vec1[lane * 2];
    float ps[8], pd[8];
#pragma unroll
    for (int r = 0; r < 8; r++) {
        *(ull*)&sm->A[(r0 + r) * HID + lane * 2] = acc[r];
        float2 a = unpk(acc[r]);
        ps[r] = a.x * s2.x + a.y * s2.y;
        pd[r] = a.x * d2.x + a.y * d2.y;
    }
#pragma unroll
    for (int o = 16; o; o >>= 1) {
#pragma unroll
        for (int r = 0; r < 8; r++) {
            ps[r] += __shfl_xor_sync(0xffffffffu, ps[r], o);
            pd[r] += __shfl_xor_sync(0xffffffffu, pd[r], o);
        }
    }
    if (lane < 8) {
        int v = r0 + lane;
        float a = ps[lane], b = pd[lane];
        sm->alS[v] = a;
        sm->alD[v] = b;
        float t = a + b;
        sm->alE[v] = __expf(fmaf(0.4f, fabsf(t), 0.6f * t));   // exp(lrelu(t,0.2))
    }
}

// ---- one GATConv layer (with self-loops), fully in SMEM ----
__device__ void gat_layer(SM* sm, const float* __restrict__ Wg,
                          const float* __restrict__ as_, const float* __restrict__ ad_,
                          const float* __restrict__ bias,
                          int tid, int wid, int lane)
{
    for (int i = tid; i < HID * HID; i += GT) sm->W[i] = Wg[i];
    if (tid < HID) { sm->vec0[tid] = as_[tid]; sm->vec1[tid] = ad_[tid]; sm->vec2[tid] = bias[tid]; }
    __syncthreads();

    gemm64_att(sm, wid, lane);     // A = H @ W, plus alS/alD/alE
    __syncthreads();

    // fused logit+exp pass (edge-parallel); one LDS.16 gives both s and d
#pragma unroll
    for (int i = tid; i < EPG; i += GT) {
        int sd = sm->csd[i];
        int s = sd & 255, d = sd >> 8;
        float t = sm->alS[s] + sm->alD[d];
        float2 w;
        w.x = __expf(fmaf(0.4f, fabsf(t), 0.6f * t));
        w.y = __int_as_float(s << 8);
        sm->ae[i] = w;
    }
    __syncthreads();

    // single-pass aggregate + normalize (warp per destination)
    const char* Ab = (const char*)sm->A + lane * 8;
    for (int v = wid; v < NPG; v += NW) {
        ull acc = 0ull; float ps = 0.f;
        seg_aggregate(sm, Ab, sm->off[v], sm->off[v + 1], acc, ps);
        float el = sm->alE[v];
        fma2(acc, pk1(el), *(const ull*)(Ab + (v << 8)));
        float inv = __fdividef(1.f, ps + el + 1e-16f);
        float2 r  = unpk(acc);
        float2 b2 = *(const float2*)&sm->vec2[lane * 2];
        float2 o;
        o.x = fmaxf(fmaf(r.x, inv, b2.x), 0.f);
        o.y = fmaxf(fmaf(r.y, inv, b2.y), 0.f);
        *(float2*)&sm->H[v * HID + lane * 2] = o;
    }
    __syncthreads();
}

// ---- kernel 1: full 3-layer GNN, one CTA per graph, 2 CTAs/SM ----
__global__ void __launch_bounds__(GT, 2) gnn_kernel(
    const float* __restrict__ x, const int* __restrict__ ei,
    const float* __restrict__ Wl, const float* __restrict__ bl,
    const float* __restrict__ Wr, const float* __restrict__ br,
    const float* __restrict__ attv, const float* __restrict__ bv2,
    const float* __restrict__ Wg1, const float* __restrict__ as1,
    const float* __restrict__ ad1, const float* __restrict__ bg1,
    const float* __restrict__ Wg2, const float* __restrict__ as2,
    const float* __restrict__ ad2, const float* __restrict__ bg2,
    const float* __restrict__ lngp, const float* __restrict__ lnbp)
{
    extern __shared__ char smraw[];
    SM* sm = (SM*)smraw;
    int tid = threadIdx.x, lane = tid & 31, wid = tid >> 5;
    int g = blockIdx.x, base = g * NPG;
    const int* srcp = ei + (size_t)g * EPG;
    const int* dstp = ei + (size_t)NGRAPH * EPG + (size_t)g * EPG;

    // ---- load inputs, count in-degrees ----
    for (int i = tid; i < NPG * 4; i += GT) sm->xin[i] = x[(size_t)base * 4 + i];
    if (tid < HID) { sm->lng[tid] = lngp[tid]; sm->lnb[tid] = lnbp[tid]; }
    for (int i = tid; i < NPG; i += GT) sm->cnt[i] = 0;
    __syncthreads();
    for (int i = tid; i < EPG; i += GT) atomicAdd(&sm->cnt[dstp[i] - base], 1);
    __syncthreads();

    // exclusive scan of counts -> off
    int myv = 0, sc = 0;
    if (tid < NPG) {
        myv = sm->cnt[tid]; sc = myv;
#pragma unroll
        for (int o = 1; o < 32; o <<= 1) {
            int n = __shfl_up_sync(0xffffffffu, sc, o);
            if (lane >= o) sc += n;
        }
        if (lane == 31) sm->scanw[wid] = sc;
    }
    __syncthreads();
    if (tid < NPG) {
        int add = 0;
        for (int i = 0; i < wid; i++) add += sm->scanw[i];
        sm->off[tid] = add + sc - myv;
    }
    if (tid == 0) sm->off[NPG] = EPG;
    __syncthreads();
    if (tid < NPG) sm->cnt[tid] = sm->off[tid];
    __syncthreads();
    // scatter into materialized CSR: single u16 store per edge
    for (int i = tid; i < EPG; i += GT) {
        int s = srcp[i] - base, d = dstp[i] - base;
        int pos = atomicAdd(&sm->cnt[d], 1);
        sm->csd[pos] = (unsigned short)(s | (d << 8));
    }

    // ---- GATv2 layer ----
    for (int i = tid; i < 4 * HID; i += GT) { sm->W[i] = Wl[i]; sm->W[4 * HID + i] = Wr[i]; }
    if (tid < HID) { sm->vec0[tid] = bl[tid]; sm->vec1[tid] = br[tid];
                     sm->vec2[tid] = attv[tid]; sm->vec3[tid] = bv2[tid]; }
    __syncthreads();
    {   // xl -> A, xr -> H  (IN = 4, tiny)
        int k = tid & (HID - 1), vg = tid >> 6;
#pragma unroll 4
        for (int r = 0; r < 16; r++) {
            int v = vg * 16 + r;
            float a = sm->vec0[k], b = sm->vec1[k];
#pragma unroll
            for (int i = 0; i < 4; i++) {
                float xv = sm->xin[v * 4 + i];
                a = fmaf(xv, sm->W[i * HID + k], a);
                b = fmaf(xv, sm->W[4 * HID + i * HID + k], b);
            }
            sm->A[v * HID + k] = a;
            sm->H[v * HID + k] = b;
        }
    }
    __syncthreads();
    // v2 logits fused with exp: half-warp per edge over CONTIGUOUS per-warp
    // chunks (CSR dst-runs preserved) with xr cached in registers.
    {
        int hl = lane & 15, half = lane >> 4;
        float4 at = *(const float4*)&sm->vec2[hl * 4];
        int j0 = wid * (EPG / NW);
        int dcur = -1;
        float4 xr = make_float4(0.f, 0.f, 0.f, 0.f);
        for (int jj = j0; jj < j0 + EPG / NW; jj += 2) {
            int j = jj + half;
            int sd = sm->csd[j];
            int s = sd & 255, d = sd >> 8;
            if (d != dcur) {               // predicated, rare
                xr = *(const float4*)&sm->H[d * HID + hl * 4];
                dcur = d;
            }
            float4 xl = *(const float4*)&sm->A[s * HID + hl * 4];
            float s0 = xl.x + xr.x, s1 = xl.y + xr.y;
            float s2 = xl.z + xr.z, s3 = xl.w + xr.w;
            float p = fmaf(s0, at.x, fmaf(s1, at.y, fmaf(s2, at.z, s3 * at.w)));
            float q = fmaf(fabsf(s0), at.x, fmaf(fabsf(s1), at.y,
                      fmaf(fabsf(s2), at.z, fabsf(s3) * at.w)));
            float t = fmaf(0.4f, q, 0.6f * p);
#pragma unroll
            for (int o = 8; o; o >>= 1) t += __shfl_xor_sync(0xffffffffu, t, o);
            if (hl == 0)
                sm->ae[j] = make_float2(__expf(t), __int_as_float(s << 8));
        }
    }
    __syncthreads();
    // aggregate + bias + lrelu(0.01) + layernorm -> H   (no self-loop in GATv2)
    {
        const char* Ab = (const char*)sm->A + lane * 8;
        for (int v = wid; v < NPG; v += NW) {
            ull acc = 0ull; float ps = 0.f;
            seg_aggregate(sm, Ab, sm->off[v], sm->off[v + 1], acc, ps);
            float inv = __fdividef(1.f, ps + 1e-16f);
            float2 r  = unpk(acc);
            float2 b2 = *(const float2*)&sm->vec3[lane * 2];
            float u0 = fmaf(r.x, inv, b2.x);
            float u1 = fmaf(r.y, inv, b2.y);
            float t0 = fmaf(0.495f, fabsf(u0), 0.505f * u0);   // lrelu 0.01
            float t1 = fmaf(0.495f, fabsf(u1), 0.505f * u1);
            float mean = wsum(t0 + t1) * (1.f / 64.f);
            float d0 = t0 - mean, d1 = t1 - mean;
            float var = wsum(d0 * d0 + d1 * d1) * (1.f / 64.f);
            float rstd = rsqrtf(var + 1e-5f);
            float2 gg = *(const float2*)&sm->lng[lane * 2];
            float2 bb = *(const float2*)&sm->lnb[lane * 2];
            float2 o;
            o.x = fmaf(d0 * rstd, gg.x, bb.x);
            o.y = fmaf(d1 * rstd, gg.y, bb.y);
            *(float2*)&sm->H[v * HID + lane * 2] = o;
        }
    }
    __syncthreads();

    // ---- GAT layers 1 & 2 ----
    gat_layer(sm, Wg1, as1, ad1, bg1, tid, wid, lane);
    gat_layer(sm, Wg2, as2, ad2, bg2, tid, wid, lane);

    // ---- write final features ----
    const float4* Hv = (const float4*)sm->H;
    float4* outp = (float4*)(g_h + (size_t)g * NPG * HID);
    for (int i = tid; i < NPG * HID / 4; i += GT) outp[i] = Hv[i];
}

// ---- kernel 2: head GEMM via tensor cores, 3xTF32 split (fp32 accuracy) ----
// grid (8, KSPLIT): CTA tile M128 x N128 x K512. 256 thr = 8 warps (4m x 2n),
// warp tile 32x64. A split (hi/lo) in smem; B fp32 in smem, split in regs.
__global__ void __launch_bounds__(256) head_gemm(const float* __restrict__ W1)
{
    __shared__ unsigned Ah[128][20], Al[128][20];   // pad 20: conflict-free frag loads
    __shared__ float    Bs[16][136];                // pad 136: conflict-free frag loads
    int m0 = blockIdx.x * 128;
    int kbase = blockIdx.y * (8192 / KSPLIT);       // 512 k per CTA, 32 chunks of 16
    int tid = threadIdx.x;
    int wid = tid >> 5, lane = tid & 31;
    int gq = lane >> 2, tig = lane & 3;
    int mb = (wid & 3) * 32, nb = (wid >> 2) * 64;

    int ar = tid >> 1, aq = (tid & 1) * 8;          // A: 2 float4 / thread
    int brr = tid >> 4, bc = (tid & 15) * 8;        // B: 2 float4 / thread
    const float* gA = &g_h[(size_t)(m0 + ar) * 8192 + kbase + aq];
    const float* gB = &W1[(size_t)(kbase + brr) * 128 + bc];

    float C[2][8][4];
#pragma unroll
    for (int f = 0; f < 2; f++)
#pragma unroll
        for (int j = 0; j < 8; j++)
#pragma unroll
            for (int c = 0; c < 4; c++) C[f][j][c] = 0.f;

    // prologue: fetch chunk 0
    float4 pa0 = *(const float4*)gA;
    float4 pa1 = *(const float4*)(gA + 4);
    float4 pb0 = *(const float4*)gB;
    float4 pb1 = *(const float4*)(gB + 4);

#pragma unroll 1
    for (int ch = 0; ch < 32; ch++) {
        __syncthreads();    // previous chunk's compute done
        {   // split-convert A and store hi/lo; store B fp32
            float a8[8] = {pa0.x, pa0.y, pa0.z, pa0.w, pa1.x, pa1.y, pa1.z, pa1.w};
            unsigned h8[8], l8[8];
#pragma unroll
            for (int i = 0; i < 8; i++) {
                h8[i] = cvt_tf32(a8[i]);
                l8[i] = cvt_tf32(a8[i] - __uint_as_float(h8[i]));
            }
            *(uint4*)&Ah[ar][aq]     = make_uint4(h8[0], h8[1], h8[2], h8[3]);
            *(uint4*)&Ah[ar][aq + 4] = make_uint4(h8[4], h8[5], h8[6], h8[7]);
            *(uint4*)&Al[ar][aq]     = make_uint4(l8[0], l8[1], l8[2], l8[3]);
            *(uint4*)&Al[ar][aq + 4] = make_uint4(l8[4], l8[5], l8[6], l8[7]);
            *(float4*)&Bs[brr][bc]     = pb0;
            *(float4*)&Bs[brr][bc + 4] = pb1;
        }
        __syncthreads();    // smem ready
        if (ch + 1 < 32) {  // prefetch next chunk under compute
            pa0 = *(const float4*)(gA + (ch + 1) * 16);
            pa1 = *(const float4*)(gA + (ch + 1) * 16 + 4);
            pb0 = *(const float4*)(gB + (size_t)(ch + 1) * 2048);
            pb1 = *(const float4*)(gB + (size_t)(ch + 1) * 2048 + 4);
        }
#pragma unroll
        for (int k8 = 0; k8 < 16; k8 += 8) {
            unsigned ah[2][4], al[2][4];
#pragma unroll
            for (int f = 0; f < 2; f++) {
                int r = mb + f * 16 + gq;
                ah[f][0] = Ah[r][k8 + tig];         al[f][0] = Al[r][k8 + tig];
                ah[f][1] = Ah[r + 8][k8 + tig];     al[f][1] = Al[r + 8][k8 + tig];
                ah[f][2] = Ah[r][k8 + tig + 4];     al[f][2] = Al[r][k8 + tig + 4];
                ah[f][3] = Ah[r + 8][k8 + tig + 4]; al[f][3] = Al[r + 8][k8 + tig + 4];
            }
#pragma unroll
            for (int j = 0; j < 8; j++) {
                int n = nb + j * 8 + gq;
                float v0 = Bs[k8 + tig][n], v1 = Bs[k8 + tig + 4][n];
                unsigned bh[2], bl[2];
                bh[0] = cvt_tf32(v0); bl[0] = cvt_tf32(v0 - __uint_as_float(bh[0]));
                bh[1] = cvt_tf32(v1); bl[1] = cvt_tf32(v1 - __uint_as_float(bh[1]));
#pragma unroll
                for (int f = 0; f < 2; f++) {
                    mma_tf32(C[f][j], ah[f], bh);
                    mma_tf32(C[f][j], al[f], bh);
                    mma_tf32(C[f][j], ah[f], bl);
                }
            }
        }
    }
    float* outp = g_hp[blockIdx.y];
#pragma unroll
    for (int f = 0; f < 2; f++)
#pragma unroll
        for (int j = 0; j < 8; j++) {
            int row = m0 + mb + f * 16 + gq;
            int col = nb + j * 8 + 2 * tig;
            *(float2*)&outp[(size_t)row * 128 + col]       = make_float2(C[f][j][0], C[f][j][1]);
            *(float2*)&outp[(size_t)(row + 8) * 128 + col] = make_float2(C[f][j][2], C[f][j][3]);
        }
}

// ---- kernel 3: reduce partials + bias, lrelu, @W2, sigmoid; one warp per graph ----
__global__ void head_final(const float* __restrict__ W2, const float* __restrict__ b2,
                           const float* __restrict__ b1, float* __restrict__ outp)
{
    int g = blockIdx.x * 8 + (threadIdx.x >> 5);
    int lane = threadIdx.x & 31;
    float4 s = make_float4(0.f, 0.f, 0.f, 0.f);
#pragma unroll
    for (int ky = 0; ky < KSPLIT; ky++) {
        float4 p = *(const float4*)&g_hp[ky][(size_t)g * 128 + lane * 4];
        s.x += p.x; s.y += p.y; s.z += p.z; s.w += p.w;
    }
    float4 bb = *(const float4*)&b1[lane * 4];
    s.x += bb.x; s.y += bb.y; s.z += bb.z; s.w += bb.w;
    s.x = fmaf(0.495f, fabsf(s.x), 0.505f * s.x);
    s.y = fmaf(0.495f, fabsf(s.y), 0.505f * s.y);
    s.z = fmaf(0.495f, fabsf(s.z), 0.505f * s.z);
    s.w = fmaf(0.495f, fabsf(s.w), 0.505f * s.w);
    float4 w = *(const float4*)&W2[lane * 4];
    float p = s.x * w.x + s.y * w.y + s.z * w.z + s.w * w.w;
    p = wsum(p);
    if (lane == 0) outp[g] = 1.f / (1.f + expf(-(p + b2[0])));
}

extern "C" void kernel_launch(void* const* d_in, const int* in_sizes, int n_in,
                              void* d_out, int out_size)
{
    const float* x    = (const float*)d_in[0];
    const int*   ei   = (const int*)  d_in[1];
    const float* Wl   = (const float*)d_in[2];
    const float* bl   = (const float*)d_in[3];
    const float* Wr   = (const float*)d_in[4];
    const float* br   = (const float*)d_in[5];
    const float* attv = (const float*)d_in[6];
    const float* bv2  = (const float*)d_in[7];
    const float* Wg1  = (const float*)d_in[8];
    const float* as1  = (const float*)d_in[9];
    const float* ad1  = (const float*)d_in[10];
    const float* bg1  = (const float*)d_in[11];
    const float* Wg2  = (const float*)d_in[12];
    const float* as2  = (const float*)d_in[13];
    const float* ad2  = (const float*)d_in[14];
    const float* bg2  = (const float*)d_in[15];
    const float* lng  = (const float*)d_in[16];
    const float* lnb  = (const float*)d_in[17];
    const float* W1   = (const float*)d_in[18];
    const float* b1   = (const float*)d_in[19];
    const float* W2   = (const float*)d_in[20];
    const float* b2   = (const float*)d_in[21];
    float* outp = (float*)d_out;

    int smem = (int)sizeof(SM);
    cudaFuncSetAttribute(gnn_kernel, cudaFuncAttributeMaxDynamicSharedMemorySize, smem);

    gnn_kernel<<<NGRAPH, GT, smem>>>(x, ei, Wl, bl, Wr, br, attv, bv2,
                                     Wg1, as1, ad1, bg1, Wg2, as2, ad2, bg2, lng, lnb);
    head_gemm<<<dim3(8, KSPLIT), 256>>>(W1);
    head_final<<<NGRAPH / 8, 256>>>(W2, b2, b1, outp);
}